// round 9
// baseline (speedup 1.0000x reference)
#include <cuda_runtime.h>
#include <cstdint>

#define SEQ   2048
#define DM    768
#define NH    12
#define DH    64
#define BATCH 4
#define M_TOTAL (BATCH * SEQ)   // 8192

// Head-split projection scratch: [b, h, s, d] fp32
__device__ float g_wq[BATCH * NH * SEQ * DH];
__device__ float g_wk[BATCH * NH * SEQ * DH];
__device__ float g_wv[BATCH * NH * SEQ * DH];

// ---------------------------------------------------------------------------
// Precision helpers.
//  - tf32 single-pass operands (P, V): RN via +0x1000 (HW truncates low 13).
//  - bf16 3-term split for score/proj paths: hi = RN_bf16(x), lo = RN_bf16(x-hi).
// ---------------------------------------------------------------------------
__device__ __forceinline__ uint32_t rn_bits(float x) {
    return __float_as_uint(x) + 0x1000u;
}
__device__ __forceinline__ uint32_t pack_bf16(float e, float o) {
    uint32_t r;
    asm("cvt.rn.bf16x2.f32 %0, %1, %2;" : "=r"(r) : "f"(o), "f"(e));
    return r;
}
__device__ __forceinline__ void bf_split(float e, float o, uint32_t& h, uint32_t& l) {
    h = pack_bf16(e, o);
    float he = __uint_as_float(h << 16);
    float ho = __uint_as_float(h & 0xFFFF0000u);
    l = pack_bf16(e - he, o - ho);
}

// m16n8k8 tf32 mma, C += A*B
__device__ __forceinline__ void mma8(float* c,
                                     uint32_t a0, uint32_t a1, uint32_t a2, uint32_t a3,
                                     uint32_t b0, uint32_t b1) {
    asm volatile(
        "mma.sync.aligned.m16n8k8.row.col.f32.tf32.tf32.f32 "
        "{%0,%1,%2,%3}, {%4,%5,%6,%7}, {%8,%9}, {%0,%1,%2,%3};\n"
        : "+f"(c[0]), "+f"(c[1]), "+f"(c[2]), "+f"(c[3])
        : "r"(a0), "r"(a1), "r"(a2), "r"(a3), "r"(b0), "r"(b1));
}
// m16n8k16 bf16 mma, C += A*B
__device__ __forceinline__ void mma16(float* c,
                                      uint32_t a0, uint32_t a1, uint32_t a2, uint32_t a3,
                                      uint32_t b0, uint32_t b1) {
    asm volatile(
        "mma.sync.aligned.m16n8k16.row.col.f32.bf16.bf16.f32 "
        "{%0,%1,%2,%3}, {%4,%5,%6,%7}, {%8,%9}, {%0,%1,%2,%3};\n"
        : "+f"(c[0]), "+f"(c[1]), "+f"(c[2]), "+f"(c[3])
        : "r"(a0), "r"(a1), "r"(a2), "r"(a3), "r"(b0), "r"(b1));
}

// cp.async 16B, L1-bypass
__device__ __forceinline__ void cp16(uint32_t smem_addr, const void* gptr) {
    asm volatile("cp.async.cg.shared.global [%0], [%1], 16;\n"
                 :: "r"(smem_addr), "l"(gptr));
}
__device__ __forceinline__ void cp_commit() {
    asm volatile("cp.async.commit_group;\n");
}

// ---------------------------------------------------------------------------
// Fused projection GEMM: z in {0,1,2} selects (Q,K,V). (unchanged from R7)
// ---------------------------------------------------------------------------
__global__ __launch_bounds__(256) void proj_fused_kernel(
    const float* __restrict__ Xq, const float* __restrict__ Xk, const float* __restrict__ Xv,
    const float* __restrict__ Wq, const float* __restrict__ bq,
    const float* __restrict__ Wk, const float* __restrict__ bk,
    const float* __restrict__ Wv, const float* __restrict__ bv,
    float* __restrict__ Oq, float* __restrict__ Ok, float* __restrict__ Ov)
{
    const int z = blockIdx.z;
    const float* X    = (z == 0) ? Xq : (z == 1) ? Xk : Xv;
    const float* W    = (z == 0) ? Wq : (z == 1) ? Wk : Wv;
    const float* bias = (z == 0) ? bq : (z == 1) ? bk : bv;
    float* Out        = (z == 0) ? Oq : (z == 1) ? Ok : Ov;
    const bool PRECISE = (z != 2);

    __shared__ float Xs[2][128][24];
    __shared__ float Ws[2][64][24];

    const int tid  = threadIdx.x;
    const int lane = tid & 31;
    const int warp = tid >> 5;
    const int wm   = warp & 3;
    const int wn   = warp >> 2;
    const int bm   = blockIdx.y * 128;
    const int bn   = blockIdx.x * 64;

    const int g  = lane >> 2;
    const int tg = lane & 3;

    float acc[2][4][4];
#pragma unroll
    for (int i = 0; i < 2; i++)
#pragma unroll
        for (int j = 0; j < 4; j++)
#pragma unroll
            for (int r = 0; r < 4; r++) acc[i][j][r] = 0.f;

    const uint32_t xs_base = (uint32_t)__cvta_generic_to_shared(&Xs[0][0][0]);
    const uint32_t ws_base = (uint32_t)__cvta_generic_to_shared(&Ws[0][0][0]);
    const int xrow0 = tid >> 2,  xc0 = (tid & 3) * 4;
    const int wrow  = tid >> 2,  wc  = (tid & 3) * 4;

    const int NT = DM / 16;   // 48

    auto issue = [&](int kt) {
        const int k0 = kt * 16;
        const uint32_t xb = xs_base + (uint32_t)((kt & 1) * 128 * 24 * 4);
        const uint32_t wb = ws_base + (uint32_t)((kt & 1) * 64 * 24 * 4);
        cp16(xb + (uint32_t)((xrow0      ) * 24 + xc0) * 4,
             X + (size_t)(bm + xrow0) * DM + k0 + xc0);
        cp16(xb + (uint32_t)((xrow0 + 64 ) * 24 + xc0) * 4,
             X + (size_t)(bm + xrow0 + 64) * DM + k0 + xc0);
        cp16(wb + (uint32_t)(wrow * 24 + wc) * 4,
             W + (size_t)(bn + wrow) * DM + k0 + wc);
        cp_commit();
    };

    issue(0);
    issue(1);

    for (int kt = 0; kt < NT; kt++) {
        if (kt + 1 < NT) asm volatile("cp.async.wait_group 1;\n");
        else             asm volatile("cp.async.wait_group 0;\n");
        __syncthreads();
        const int buf = kt & 1;

        if (PRECISE) {
            uint32_t ah[2][4], al[2][4], bh[4][2], bl[4][2];
#pragma unroll
            for (int mt = 0; mt < 2; mt++) {
                const int rb = wm * 32 + mt * 16;
                float2 A0 = *reinterpret_cast<const float2*>(&Xs[buf][rb + g    ][2 * tg]);
                float2 A1 = *reinterpret_cast<const float2*>(&Xs[buf][rb + g + 8][2 * tg]);
                float2 A2 = *reinterpret_cast<const float2*>(&Xs[buf][rb + g    ][2 * tg + 8]);
                float2 A3 = *reinterpret_cast<const float2*>(&Xs[buf][rb + g + 8][2 * tg + 8]);
                bf_split(A0.x, A0.y, ah[mt][0], al[mt][0]);
                bf_split(A1.x, A1.y, ah[mt][1], al[mt][1]);
                bf_split(A2.x, A2.y, ah[mt][2], al[mt][2]);
                bf_split(A3.x, A3.y, ah[mt][3], al[mt][3]);
            }
#pragma unroll
            for (int nt = 0; nt < 4; nt++) {
                const int nb = wn * 32 + nt * 8;
                float2 B0 = *reinterpret_cast<const float2*>(&Ws[buf][nb + g][2 * tg]);
                float2 B1 = *reinterpret_cast<const float2*>(&Ws[buf][nb + g][2 * tg + 8]);
                bf_split(B0.x, B0.y, bh[nt][0], bl[nt][0]);
                bf_split(B1.x, B1.y, bh[nt][1], bl[nt][1]);
            }
#pragma unroll
            for (int mt = 0; mt < 2; mt++)
#pragma unroll
                for (int nt = 0; nt < 4; nt++) {
                    mma16(acc[mt][nt], ah[mt][0], ah[mt][1], ah[mt][2], ah[mt][3],
                          bh[nt][0], bh[nt][1]);
                    mma16(acc[mt][nt], ah[mt][0], ah[mt][1], ah[mt][2], ah[mt][3],
                          bl[nt][0], bl[nt][1]);
                    mma16(acc[mt][nt], al[mt][0], al[mt][1], al[mt][2], al[mt][3],
                          bh[nt][0], bh[nt][1]);
                }
        } else {
#pragma unroll
            for (int ks = 0; ks < 2; ks++) {
                const int kk = ks * 8;
                uint32_t ah[2][4], bh[4][2];
#pragma unroll
                for (int mt = 0; mt < 2; mt++) {
                    const int rb = wm * 32 + mt * 16;
                    ah[mt][0] = rn_bits(Xs[buf][rb + g    ][kk + tg]);
                    ah[mt][1] = rn_bits(Xs[buf][rb + g + 8][kk + tg]);
                    ah[mt][2] = rn_bits(Xs[buf][rb + g    ][kk + tg + 4]);
                    ah[mt][3] = rn_bits(Xs[buf][rb + g + 8][kk + tg + 4]);
                }
#pragma unroll
                for (int nt = 0; nt < 4; nt++) {
                    const int nb = wn * 32 + nt * 8;
                    bh[nt][0] = rn_bits(Ws[buf][nb + g][kk + tg]);
                    bh[nt][1] = rn_bits(Ws[buf][nb + g][kk + tg + 4]);
                }
#pragma unroll
                for (int mt = 0; mt < 2; mt++)
#pragma unroll
                    for (int nt = 0; nt < 4; nt++)
                        mma8(acc[mt][nt], ah[mt][0], ah[mt][1], ah[mt][2], ah[mt][3],
                             bh[nt][0], bh[nt][1]);
            }
        }
        __syncthreads();
        if (kt + 2 < NT) issue(kt + 2);
    }

#pragma unroll
    for (int mt = 0; mt < 2; mt++) {
#pragma unroll
        for (int nt = 0; nt < 4; nt++) {
            const int n  = bn + wn * 32 + nt * 8 + 2 * tg;
            const int h  = n / DH;
            const int d  = n % DH;
            const float b0 = bias[n];
            const float b1 = bias[n + 1];
#pragma unroll
            for (int rr = 0; rr < 2; rr++) {
                const int m = bm + wm * 32 + mt * 16 + g + rr * 8;
                const int bb = m / SEQ;
                const int s  = m % SEQ;
                float2 v;
                v.x = acc[mt][nt][rr * 2 + 0] + b0;
                v.y = acc[mt][nt][rr * 2 + 1] + b1;
                *reinterpret_cast<float2*>(
                    Out + (((size_t)(bb * NH + h)) * SEQ + s) * DH + d) = v;
            }
        }
    }
}

// ---------------------------------------------------------------------------
// Flash attention. 64 q rows/block, 4 warps, key tiles of 32, double-buffered
// cp.async. K is cooperatively pre-split ONCE per tile into packed bf16x2
// (hi,lo) uint2 smem -> score loop is pure LDS.64 + mma16 (zero ALU).
// PV: single-pass RN tf32.
// ---------------------------------------------------------------------------
__global__ __launch_bounds__(128, 4) void flash_mma_kernel(
    const float* __restrict__ Qh,
    const float* __restrict__ Kh,
    const float* __restrict__ Vh,
    float* __restrict__ out)
{
    __shared__ float Kraw[2][32][68];  // cp.async target (raw K)
    __shared__ uint2 Kpk[32][36];      // packed (hi,lo) bf16x2 per k-pair; single buf
    __shared__ float Vs[2][32][72];    // raw V
    __shared__ float Ps[4][16][36];    // per-warp P tile (pre-rounded bits)

    const int tid  = threadIdx.x;
    const int lane = tid & 31;
    const int warp = tid >> 5;
    const int g    = lane >> 2;
    const int tg   = lane & 3;

    const int b  = blockIdx.z;
    const int h  = blockIdx.y;
    const int q0 = blockIdx.x * 64;
    const size_t base = ((size_t)(b * NH + h)) * SEQ * DH;

    const uint32_t ks_base = (uint32_t)__cvta_generic_to_shared(&Kraw[0][0][0]);
    const uint32_t vs_base = (uint32_t)__cvta_generic_to_shared(&Vs[0][0][0]);

    auto issue = [&](int kt) {
        const uint32_t kb = ks_base + (uint32_t)((kt & 1) * 32 * 68 * 4);
        const uint32_t vb = vs_base + (uint32_t)((kt & 1) * 32 * 72 * 4);
        const float* kp = Kh + base + (size_t)(kt * 32) * DH;
        const float* vp = Vh + base + (size_t)(kt * 32) * DH;
#pragma unroll
        for (int i = 0; i < 4; i++) {
            const int idx = i * 128 + tid;
            const int row = idx >> 4;
            const int c   = (idx & 15) * 4;
            cp16(kb + (uint32_t)(row * 68 + c) * 4, kp + row * 64 + c);
            cp16(vb + (uint32_t)(row * 72 + c) * 4, vp + row * 64 + c);
        }
        cp_commit();
    };

    // Hoisted Q fragments (bf16 hi/lo): 4 ksteps x 4 regs each
    uint32_t qh[4][4], ql[4][4];
    {
        const float* q0p = Qh + base + (size_t)(q0 + warp * 16 + g) * DH;
        const float* q1p = q0p + 8 * DH;
#pragma unroll
        for (int s = 0; s < 4; s++) {
            const int c0 = s * 16 + 2 * tg;
            float2 A0 = *reinterpret_cast<const float2*>(q0p + c0);
            float2 A1 = *reinterpret_cast<const float2*>(q1p + c0);
            float2 A2 = *reinterpret_cast<const float2*>(q0p + c0 + 8);
            float2 A3 = *reinterpret_cast<const float2*>(q1p + c0 + 8);
            bf_split(A0.x, A0.y, qh[s][0], ql[s][0]);
            bf_split(A1.x, A1.y, qh[s][1], ql[s][1]);
            bf_split(A2.x, A2.y, qh[s][2], ql[s][2]);
            bf_split(A3.x, A3.y, qh[s][3], ql[s][3]);
        }
    }

    issue(0);
    issue(1);

    float oacc[8][4];
#pragma unroll
    for (int dt = 0; dt < 8; dt++)
#pragma unroll
        for (int r = 0; r < 4; r++) oacc[dt][r] = 0.f;
    float mrow0 = -1e30f, mrow1 = -1e30f;
    float lrow0 = 0.f,    lrow1 = 0.f;

    // split-phase mapping: row = tid>>2, pairs p = tg + 4j (bank-conflict-free)
    const int srow = tid >> 2;

    const int NT = SEQ / 32;   // 64

    for (int kt = 0; kt < NT; kt++) {
        if (kt + 1 < NT) asm volatile("cp.async.wait_group 1;\n");
        else             asm volatile("cp.async.wait_group 0;\n");
        __syncthreads();
        const int buf = kt & 1;

        // ---- co-op split: Kraw -> packed bf16x2 hi/lo (8 pairs per lane) ----
#pragma unroll
        for (int j = 0; j < 8; j++) {
            const int p = tg + 4 * j;                 // pair index 0..31
            float2 kvp = *reinterpret_cast<const float2*>(&Kraw[buf][srow][2 * p]);
            uint32_t hi, lo;
            bf_split(kvp.x, kvp.y, hi, lo);
            Kpk[srow][p] = make_uint2(hi, lo);
        }
        __syncthreads();

        // ---- Scores: S (16 x 32) per warp, 3x bf16-k16, pure LDS+mma ----
        float sacc[4][4];
#pragma unroll
        for (int nt = 0; nt < 4; nt++)
#pragma unroll
            for (int r = 0; r < 4; r++) sacc[nt][r] = 0.f;

#pragma unroll
        for (int s = 0; s < 4; s++) {
#pragma unroll
            for (int nt = 0; nt < 4; nt++) {
                uint2 w0 = Kpk[nt * 8 + g][s * 8 + tg];
                uint2 w1 = Kpk[nt * 8 + g][s * 8 + tg + 4];
                mma16(sacc[nt], qh[s][0], qh[s][1], qh[s][2], qh[s][3], w0.x, w1.x);
                mma16(sacc[nt], qh[s][0], qh[s][1], qh[s][2], qh[s][3], w0.y, w1.y);
                mma16(sacc[nt], ql[s][0], ql[s][1], ql[s][2], ql[s][3], w0.x, w1.x);
            }
        }

        // ---- Online softmax ----
        float tmax0 = sacc[0][0], tmax1 = sacc[0][2];
#pragma unroll
        for (int nt = 0; nt < 4; nt++) {
            tmax0 = fmaxf(tmax0, fmaxf(sacc[nt][0], sacc[nt][1]));
            tmax1 = fmaxf(tmax1, fmaxf(sacc[nt][2], sacc[nt][3]));
        }
        tmax0 = fmaxf(tmax0, __shfl_xor_sync(0xffffffff, tmax0, 1));
        tmax0 = fmaxf(tmax0, __shfl_xor_sync(0xffffffff, tmax0, 2));
        tmax1 = fmaxf(tmax1, __shfl_xor_sync(0xffffffff, tmax1, 1));
        tmax1 = fmaxf(tmax1, __shfl_xor_sync(0xffffffff, tmax1, 2));

        const float mnew0 = fmaxf(mrow0, tmax0);
        const float mnew1 = fmaxf(mrow1, tmax1);
        const float corr0 = __expf(mrow0 - mnew0);
        const float corr1 = __expf(mrow1 - mnew1);
        mrow0 = mnew0; mrow1 = mnew1;

        float ps0 = 0.f, ps1 = 0.f;
#pragma unroll
        for (int nt = 0; nt < 4; nt++) {
            sacc[nt][0] = __expf(sacc[nt][0] - mnew0);
            sacc[nt][1] = __expf(sacc[nt][1] - mnew0);
            sacc[nt][2] = __expf(sacc[nt][2] - mnew1);
            sacc[nt][3] = __expf(sacc[nt][3] - mnew1);
            ps0 += sacc[nt][0] + sacc[nt][1];
            ps1 += sacc[nt][2] + sacc[nt][3];
        }
        ps0 += __shfl_xor_sync(0xffffffff, ps0, 1);
        ps0 += __shfl_xor_sync(0xffffffff, ps0, 2);
        ps1 += __shfl_xor_sync(0xffffffff, ps1, 1);
        ps1 += __shfl_xor_sync(0xffffffff, ps1, 2);
        lrow0 = lrow0 * corr0 + ps0;
        lrow1 = lrow1 * corr1 + ps1;

#pragma unroll
        for (int dt = 0; dt < 8; dt++) {
            oacc[dt][0] *= corr0;
            oacc[dt][1] *= corr0;
            oacc[dt][2] *= corr1;
            oacc[dt][3] *= corr1;
        }

        // P tile to per-warp smem, pre-rounded (RN after HW trunc)
#pragma unroll
        for (int nt = 0; nt < 4; nt++) {
            const int col = nt * 8 + 2 * tg;
            *reinterpret_cast<uint2*>(&Ps[warp][g][col]) =
                make_uint2(rn_bits(sacc[nt][0]), rn_bits(sacc[nt][1]));
            *reinterpret_cast<uint2*>(&Ps[warp][g + 8][col]) =
                make_uint2(rn_bits(sacc[nt][2]), rn_bits(sacc[nt][3]));
        }
        __syncwarp();

        // ---- PV: O(16x64) += P(16x32) @ V(32x64); tf32, V RN at consume ----
#pragma unroll
        for (int kk = 0; kk < 4; kk++) {
            const int kc = kk * 8;
            uint32_t a0 = __float_as_uint(Ps[warp][g][kc + tg]);
            uint32_t a1 = __float_as_uint(Ps[warp][g + 8][kc + tg]);
            uint32_t a2 = __float_as_uint(Ps[warp][g][kc + tg + 4]);
            uint32_t a3 = __float_as_uint(Ps[warp][g + 8][kc + tg + 4]);
#pragma unroll
            for (int dt = 0; dt < 8; dt++) {
                uint32_t b0 = __float_as_uint(Vs[buf][kc + tg][dt * 8 + g]) + 0x1000u;
                uint32_t b1 = __float_as_uint(Vs[buf][kc + tg + 4][dt * 8 + g]) + 0x1000u;
                mma8(oacc[dt], a0, a1, a2, a3, b0, b1);
            }
        }

        __syncthreads();
        if (kt + 2 < NT) issue(kt + 2);
    }

    // Epilogue: normalize + write merged-head output [b, s, h*64 + d]
    const float inv0 = 1.f / lrow0;
    const float inv1 = 1.f / lrow1;
    const int row0 = q0 + warp * 16 + g;
    const int row1 = row0 + 8;
    float* o0 = out + ((size_t)(b * SEQ + row0)) * DM + h * DH;
    float* o1 = out + ((size_t)(b * SEQ + row1)) * DM + h * DH;
#pragma unroll
    for (int dt = 0; dt < 8; dt++) {
        const int col = dt * 8 + 2 * tg;
        float2 v0, v1;
        v0.x = oacc[dt][0] * inv0; v0.y = oacc[dt][1] * inv0;
        v1.x = oacc[dt][2] * inv1; v1.y = oacc[dt][3] * inv1;
        *reinterpret_cast<float2*>(o0 + col) = v0;
        *reinterpret_cast<float2*>(o1 + col) = v1;
    }
}

// ---------------------------------------------------------------------------
// Launch
// ---------------------------------------------------------------------------
extern "C" void kernel_launch(void* const* d_in, const int* in_sizes, int n_in,
                              void* d_out, int out_size)
{
    const float* q  = (const float*)d_in[0];
    const float* k  = (const float*)d_in[1];
    const float* v  = (const float*)d_in[2];
    const float* Wq = (const float*)d_in[3];
    const float* bq = (const float*)d_in[4];
    const float* Wk = (const float*)d_in[5];
    const float* bk = (const float*)d_in[6];
    const float* Wv = (const float*)d_in[7];
    const float* bv = (const float*)d_in[8];
    float* out = (float*)d_out;

    float *dq, *dk, *dv;
    cudaGetSymbolAddress((void**)&dq, g_wq);
    cudaGetSymbolAddress((void**)&dk, g_wk);
    cudaGetSymbolAddress((void**)&dv, g_wv);

    dim3 pgrid(DM / 64, M_TOTAL / 128, 3);     // (12, 64, 3)
    proj_fused_kernel<<<pgrid, 256>>>(q, k, v, Wq, bq, Wk, bk, Wv, bv, dq, dk, dv);

    dim3 agrid(SEQ / 64, NH, BATCH);           // (32, 12, 4)
    flash_mma_kernel<<<agrid, 128>>>(dq, dk, dv, out);
}

// round 11
// speedup vs baseline: 1.6016x; 1.6016x over previous
#include <cuda_runtime.h>
#include <cstdint>

#define SEQ   2048
#define DM    768
#define NH    12
#define DH    64
#define BATCH 4
#define M_TOTAL (BATCH * SEQ)   // 8192

// Head-split projection scratch: [b, h, s, d] fp32
__device__ float g_wq[BATCH * NH * SEQ * DH];
__device__ float g_wk[BATCH * NH * SEQ * DH];
__device__ float g_wv[BATCH * NH * SEQ * DH];

// ---------------------------------------------------------------------------
// Precision helpers.
//  - tf32 single-pass operands (P, V): RN via +0x1000 (HW truncates low 13).
//  - bf16 3-term split for score/proj paths: hi = RN_bf16(x), lo = RN_bf16(x-hi).
// ---------------------------------------------------------------------------
__device__ __forceinline__ uint32_t rn_bits(float x) {
    return __float_as_uint(x) + 0x1000u;
}
__device__ __forceinline__ uint32_t pack_bf16(float e, float o) {
    uint32_t r;
    asm("cvt.rn.bf16x2.f32 %0, %1, %2;" : "=r"(r) : "f"(o), "f"(e));
    return r;
}
__device__ __forceinline__ void bf_split(float e, float o, uint32_t& h, uint32_t& l) {
    h = pack_bf16(e, o);
    float he = __uint_as_float(h << 16);
    float ho = __uint_as_float(h & 0xFFFF0000u);
    l = pack_bf16(e - he, o - ho);
}

// m16n8k8 tf32 mma, C += A*B
__device__ __forceinline__ void mma8(float* c,
                                     uint32_t a0, uint32_t a1, uint32_t a2, uint32_t a3,
                                     uint32_t b0, uint32_t b1) {
    asm volatile(
        "mma.sync.aligned.m16n8k8.row.col.f32.tf32.tf32.f32 "
        "{%0,%1,%2,%3}, {%4,%5,%6,%7}, {%8,%9}, {%0,%1,%2,%3};\n"
        : "+f"(c[0]), "+f"(c[1]), "+f"(c[2]), "+f"(c[3])
        : "r"(a0), "r"(a1), "r"(a2), "r"(a3), "r"(b0), "r"(b1));
}
// m16n8k16 bf16 mma, C += A*B
__device__ __forceinline__ void mma16(float* c,
                                      uint32_t a0, uint32_t a1, uint32_t a2, uint32_t a3,
                                      uint32_t b0, uint32_t b1) {
    asm volatile(
        "mma.sync.aligned.m16n8k16.row.col.f32.bf16.bf16.f32 "
        "{%0,%1,%2,%3}, {%4,%5,%6,%7}, {%8,%9}, {%0,%1,%2,%3};\n"
        : "+f"(c[0]), "+f"(c[1]), "+f"(c[2]), "+f"(c[3])
        : "r"(a0), "r"(a1), "r"(a2), "r"(a3), "r"(b0), "r"(b1));
}

// cp.async 16B, L1-bypass
__device__ __forceinline__ void cp16(uint32_t smem_addr, const void* gptr) {
    asm volatile("cp.async.cg.shared.global [%0], [%1], 16;\n"
                 :: "r"(smem_addr), "l"(gptr));
}
__device__ __forceinline__ void cp_commit() {
    asm volatile("cp.async.commit_group;\n");
}

// ---------------------------------------------------------------------------
// Fused projection GEMM: z in {0,1,2} selects (Q,K,V). (unchanged from R8)
// ---------------------------------------------------------------------------
__global__ __launch_bounds__(256) void proj_fused_kernel(
    const float* __restrict__ Xq, const float* __restrict__ Xk, const float* __restrict__ Xv,
    const float* __restrict__ Wq, const float* __restrict__ bq,
    const float* __restrict__ Wk, const float* __restrict__ bk,
    const float* __restrict__ Wv, const float* __restrict__ bv,
    float* __restrict__ Oq, float* __restrict__ Ok, float* __restrict__ Ov)
{
    const int z = blockIdx.z;
    const float* X    = (z == 0) ? Xq : (z == 1) ? Xk : Xv;
    const float* W    = (z == 0) ? Wq : (z == 1) ? Wk : Wv;
    const float* bias = (z == 0) ? bq : (z == 1) ? bk : bv;
    float* Out        = (z == 0) ? Oq : (z == 1) ? Ok : Ov;
    const bool PRECISE = (z != 2);

    __shared__ float Xs[2][128][24];
    __shared__ float Ws[2][64][24];

    const int tid  = threadIdx.x;
    const int lane = tid & 31;
    const int warp = tid >> 5;
    const int wm   = warp & 3;
    const int wn   = warp >> 2;
    const int bm   = blockIdx.y * 128;
    const int bn   = blockIdx.x * 64;

    const int g  = lane >> 2;
    const int tg = lane & 3;

    float acc[2][4][4];
#pragma unroll
    for (int i = 0; i < 2; i++)
#pragma unroll
        for (int j = 0; j < 4; j++)
#pragma unroll
            for (int r = 0; r < 4; r++) acc[i][j][r] = 0.f;

    const uint32_t xs_base = (uint32_t)__cvta_generic_to_shared(&Xs[0][0][0]);
    const uint32_t ws_base = (uint32_t)__cvta_generic_to_shared(&Ws[0][0][0]);
    const int xrow0 = tid >> 2,  xc0 = (tid & 3) * 4;
    const int wrow  = tid >> 2,  wc  = (tid & 3) * 4;

    const int NT = DM / 16;   // 48

    auto issue = [&](int kt) {
        const int k0 = kt * 16;
        const uint32_t xb = xs_base + (uint32_t)((kt & 1) * 128 * 24 * 4);
        const uint32_t wb = ws_base + (uint32_t)((kt & 1) * 64 * 24 * 4);
        cp16(xb + (uint32_t)((xrow0      ) * 24 + xc0) * 4,
             X + (size_t)(bm + xrow0) * DM + k0 + xc0);
        cp16(xb + (uint32_t)((xrow0 + 64 ) * 24 + xc0) * 4,
             X + (size_t)(bm + xrow0 + 64) * DM + k0 + xc0);
        cp16(wb + (uint32_t)(wrow * 24 + wc) * 4,
             W + (size_t)(bn + wrow) * DM + k0 + wc);
        cp_commit();
    };

    issue(0);
    issue(1);

    for (int kt = 0; kt < NT; kt++) {
        if (kt + 1 < NT) asm volatile("cp.async.wait_group 1;\n");
        else             asm volatile("cp.async.wait_group 0;\n");
        __syncthreads();
        const int buf = kt & 1;

        if (PRECISE) {
            uint32_t ah[2][4], al[2][4], bh[4][2], bl[4][2];
#pragma unroll
            for (int mt = 0; mt < 2; mt++) {
                const int rb = wm * 32 + mt * 16;
                float2 A0 = *reinterpret_cast<const float2*>(&Xs[buf][rb + g    ][2 * tg]);
                float2 A1 = *reinterpret_cast<const float2*>(&Xs[buf][rb + g + 8][2 * tg]);
                float2 A2 = *reinterpret_cast<const float2*>(&Xs[buf][rb + g    ][2 * tg + 8]);
                float2 A3 = *reinterpret_cast<const float2*>(&Xs[buf][rb + g + 8][2 * tg + 8]);
                bf_split(A0.x, A0.y, ah[mt][0], al[mt][0]);
                bf_split(A1.x, A1.y, ah[mt][1], al[mt][1]);
                bf_split(A2.x, A2.y, ah[mt][2], al[mt][2]);
                bf_split(A3.x, A3.y, ah[mt][3], al[mt][3]);
            }
#pragma unroll
            for (int nt = 0; nt < 4; nt++) {
                const int nb = wn * 32 + nt * 8;
                float2 B0 = *reinterpret_cast<const float2*>(&Ws[buf][nb + g][2 * tg]);
                float2 B1 = *reinterpret_cast<const float2*>(&Ws[buf][nb + g][2 * tg + 8]);
                bf_split(B0.x, B0.y, bh[nt][0], bl[nt][0]);
                bf_split(B1.x, B1.y, bh[nt][1], bl[nt][1]);
            }
#pragma unroll
            for (int mt = 0; mt < 2; mt++)
#pragma unroll
                for (int nt = 0; nt < 4; nt++) {
                    mma16(acc[mt][nt], ah[mt][0], ah[mt][1], ah[mt][2], ah[mt][3],
                          bh[nt][0], bh[nt][1]);
                    mma16(acc[mt][nt], ah[mt][0], ah[mt][1], ah[mt][2], ah[mt][3],
                          bl[nt][0], bl[nt][1]);
                    mma16(acc[mt][nt], al[mt][0], al[mt][1], al[mt][2], al[mt][3],
                          bh[nt][0], bh[nt][1]);
                }
        } else {
#pragma unroll
            for (int ks = 0; ks < 2; ks++) {
                const int kk = ks * 8;
                uint32_t ah[2][4], bh[4][2];
#pragma unroll
                for (int mt = 0; mt < 2; mt++) {
                    const int rb = wm * 32 + mt * 16;
                    ah[mt][0] = rn_bits(Xs[buf][rb + g    ][kk + tg]);
                    ah[mt][1] = rn_bits(Xs[buf][rb + g + 8][kk + tg]);
                    ah[mt][2] = rn_bits(Xs[buf][rb + g    ][kk + tg + 4]);
                    ah[mt][3] = rn_bits(Xs[buf][rb + g + 8][kk + tg + 4]);
                }
#pragma unroll
                for (int nt = 0; nt < 4; nt++) {
                    const int nb = wn * 32 + nt * 8;
                    bh[nt][0] = rn_bits(Ws[buf][nb + g][kk + tg]);
                    bh[nt][1] = rn_bits(Ws[buf][nb + g][kk + tg + 4]);
                }
#pragma unroll
                for (int mt = 0; mt < 2; mt++)
#pragma unroll
                    for (int nt = 0; nt < 4; nt++)
                        mma8(acc[mt][nt], ah[mt][0], ah[mt][1], ah[mt][2], ah[mt][3],
                             bh[nt][0], bh[nt][1]);
            }
        }
        __syncthreads();
        if (kt + 2 < NT) issue(kt + 2);
    }

#pragma unroll
    for (int mt = 0; mt < 2; mt++) {
#pragma unroll
        for (int nt = 0; nt < 4; nt++) {
            const int n  = bn + wn * 32 + nt * 8 + 2 * tg;
            const int h  = n / DH;
            const int d  = n % DH;
            const float b0 = bias[n];
            const float b1 = bias[n + 1];
#pragma unroll
            for (int rr = 0; rr < 2; rr++) {
                const int m = bm + wm * 32 + mt * 16 + g + rr * 8;
                const int bb = m / SEQ;
                const int s  = m % SEQ;
                float2 v;
                v.x = acc[mt][nt][rr * 2 + 0] + b0;
                v.y = acc[mt][nt][rr * 2 + 1] + b1;
                *reinterpret_cast<float2*>(
                    Out + (((size_t)(bb * NH + h)) * SEQ + s) * DH + d) = v;
            }
        }
    }
}

// ---------------------------------------------------------------------------
// Flash attention. 64 q rows/block, 4 warps, key tiles of 32, double-buffered
// cp.async. K is cooperatively pre-split ONCE per tile into SEPARATE hi/lo
// bf16x2 arrays with row stride 36 words (36 mod 32 = 4 -> both the split-phase
// writes (4*srow+tg) and score-loop reads (4g+tg) are bank-conflict-free).
// Score loop: 4 LDS.32 + 3 mma16 per (s,nt), zero ALU. PV: single-pass RN tf32.
// ---------------------------------------------------------------------------
__global__ __launch_bounds__(128, 4) void flash_mma_kernel(
    const float* __restrict__ Qh,
    const float* __restrict__ Kh,
    const float* __restrict__ Vh,
    float* __restrict__ out)
{
    __shared__ float    Kraw[2][32][68];  // cp.async target (raw K)
    __shared__ uint32_t Khi[32][36];      // bf16x2 hi per k-pair (stride 36 words)
    __shared__ uint32_t Klo[32][36];      // bf16x2 lo per k-pair
    __shared__ float    Vs[2][32][72];    // raw V
    __shared__ float    Ps[4][16][36];    // per-warp P tile (pre-rounded bits)

    const int tid  = threadIdx.x;
    const int lane = tid & 31;
    const int warp = tid >> 5;
    const int g    = lane >> 2;
    const int tg   = lane & 3;

    const int b  = blockIdx.z;
    const int h  = blockIdx.y;
    const int q0 = blockIdx.x * 64;
    const size_t base = ((size_t)(b * NH + h)) * SEQ * DH;

    const uint32_t ks_base = (uint32_t)__cvta_generic_to_shared(&Kraw[0][0][0]);
    const uint32_t vs_base = (uint32_t)__cvta_generic_to_shared(&Vs[0][0][0]);

    auto issue = [&](int kt) {
        const uint32_t kb = ks_base + (uint32_t)((kt & 1) * 32 * 68 * 4);
        const uint32_t vb = vs_base + (uint32_t)((kt & 1) * 32 * 72 * 4);
        const float* kp = Kh + base + (size_t)(kt * 32) * DH;
        const float* vp = Vh + base + (size_t)(kt * 32) * DH;
#pragma unroll
        for (int i = 0; i < 4; i++) {
            const int idx = i * 128 + tid;
            const int row = idx >> 4;
            const int c   = (idx & 15) * 4;
            cp16(kb + (uint32_t)(row * 68 + c) * 4, kp + row * 64 + c);
            cp16(vb + (uint32_t)(row * 72 + c) * 4, vp + row * 64 + c);
        }
        cp_commit();
    };

    // Hoisted Q fragments (bf16 hi/lo): 4 ksteps x 4 regs each
    uint32_t qh[4][4], ql[4][4];
    {
        const float* q0p = Qh + base + (size_t)(q0 + warp * 16 + g) * DH;
        const float* q1p = q0p + 8 * DH;
#pragma unroll
        for (int s = 0; s < 4; s++) {
            const int c0 = s * 16 + 2 * tg;
            float2 A0 = *reinterpret_cast<const float2*>(q0p + c0);
            float2 A1 = *reinterpret_cast<const float2*>(q1p + c0);
            float2 A2 = *reinterpret_cast<const float2*>(q0p + c0 + 8);
            float2 A3 = *reinterpret_cast<const float2*>(q1p + c0 + 8);
            bf_split(A0.x, A0.y, qh[s][0], ql[s][0]);
            bf_split(A1.x, A1.y, qh[s][1], ql[s][1]);
            bf_split(A2.x, A2.y, qh[s][2], ql[s][2]);
            bf_split(A3.x, A3.y, qh[s][3], ql[s][3]);
        }
    }

    issue(0);
    issue(1);

    float oacc[8][4];
#pragma unroll
    for (int dt = 0; dt < 8; dt++)
#pragma unroll
        for (int r = 0; r < 4; r++) oacc[dt][r] = 0.f;
    float mrow0 = -1e30f, mrow1 = -1e30f;
    float lrow0 = 0.f,    lrow1 = 0.f;

    const int srow = tid >> 2;   // split-phase row 0..31

    const int NT = SEQ / 32;   // 64

    for (int kt = 0; kt < NT; kt++) {
        if (kt + 1 < NT) asm volatile("cp.async.wait_group 1;\n");
        else             asm volatile("cp.async.wait_group 0;\n");
        __syncthreads();
        const int buf = kt & 1;

        // ---- co-op split: Kraw -> Khi/Klo (8 pairs per lane, conflict-free) ----
#pragma unroll
        for (int j = 0; j < 8; j++) {
            const int p = tg + 4 * j;                 // pair index 0..31
            float2 kvp = *reinterpret_cast<const float2*>(&Kraw[buf][srow][2 * p]);
            uint32_t hi, lo;
            bf_split(kvp.x, kvp.y, hi, lo);
            Khi[srow][p] = hi;
            Klo[srow][p] = lo;
        }
        __syncthreads();

        // ---- Scores: S (16 x 32) per warp, 3x bf16-k16, pure LDS+mma ----
        float sacc[4][4];
#pragma unroll
        for (int nt = 0; nt < 4; nt++)
#pragma unroll
            for (int r = 0; r < 4; r++) sacc[nt][r] = 0.f;

#pragma unroll
        for (int s = 0; s < 4; s++) {
#pragma unroll
            for (int nt = 0; nt < 4; nt++) {
                const int kr = nt * 8 + g;
                uint32_t h0 = Khi[kr][s * 8 + tg];
                uint32_t h1 = Khi[kr][s * 8 + tg + 4];
                uint32_t l0 = Klo[kr][s * 8 + tg];
                uint32_t l1 = Klo[kr][s * 8 + tg + 4];
                mma16(sacc[nt], qh[s][0], qh[s][1], qh[s][2], qh[s][3], h0, h1);
                mma16(sacc[nt], qh[s][0], qh[s][1], qh[s][2], qh[s][3], l0, l1);
                mma16(sacc[nt], ql[s][0], ql[s][1], ql[s][2], ql[s][3], h0, h1);
            }
        }

        // ---- Online softmax ----
        float tmax0 = sacc[0][0], tmax1 = sacc[0][2];
#pragma unroll
        for (int nt = 0; nt < 4; nt++) {
            tmax0 = fmaxf(tmax0, fmaxf(sacc[nt][0], sacc[nt][1]));
            tmax1 = fmaxf(tmax1, fmaxf(sacc[nt][2], sacc[nt][3]));
        }
        tmax0 = fmaxf(tmax0, __shfl_xor_sync(0xffffffff, tmax0, 1));
        tmax0 = fmaxf(tmax0, __shfl_xor_sync(0xffffffff, tmax0, 2));
        tmax1 = fmaxf(tmax1, __shfl_xor_sync(0xffffffff, tmax1, 1));
        tmax1 = fmaxf(tmax1, __shfl_xor_sync(0xffffffff, tmax1, 2));

        const float mnew0 = fmaxf(mrow0, tmax0);
        const float mnew1 = fmaxf(mrow1, tmax1);
        const float corr0 = __expf(mrow0 - mnew0);
        const float corr1 = __expf(mrow1 - mnew1);
        mrow0 = mnew0; mrow1 = mnew1;

        float ps0 = 0.f, ps1 = 0.f;
#pragma unroll
        for (int nt = 0; nt < 4; nt++) {
            sacc[nt][0] = __expf(sacc[nt][0] - mnew0);
            sacc[nt][1] = __expf(sacc[nt][1] - mnew0);
            sacc[nt][2] = __expf(sacc[nt][2] - mnew1);
            sacc[nt][3] = __expf(sacc[nt][3] - mnew1);
            ps0 += sacc[nt][0] + sacc[nt][1];
            ps1 += sacc[nt][2] + sacc[nt][3];
        }
        ps0 += __shfl_xor_sync(0xffffffff, ps0, 1);
        ps0 += __shfl_xor_sync(0xffffffff, ps0, 2);
        ps1 += __shfl_xor_sync(0xffffffff, ps1, 1);
        ps1 += __shfl_xor_sync(0xffffffff, ps1, 2);
        lrow0 = lrow0 * corr0 + ps0;
        lrow1 = lrow1 * corr1 + ps1;

#pragma unroll
        for (int dt = 0; dt < 8; dt++) {
            oacc[dt][0] *= corr0;
            oacc[dt][1] *= corr0;
            oacc[dt][2] *= corr1;
            oacc[dt][3] *= corr1;
        }

        // P tile to per-warp smem, pre-rounded (RN after HW trunc)
#pragma unroll
        for (int nt = 0; nt < 4; nt++) {
            const int col = nt * 8 + 2 * tg;
            *reinterpret_cast<uint2*>(&Ps[warp][g][col]) =
                make_uint2(rn_bits(sacc[nt][0]), rn_bits(sacc[nt][1]));
            *reinterpret_cast<uint2*>(&Ps[warp][g + 8][col]) =
                make_uint2(rn_bits(sacc[nt][2]), rn_bits(sacc[nt][3]));
        }
        __syncwarp();

        // ---- PV: O(16x64) += P(16x32) @ V(32x64); tf32, V RN at consume ----
#pragma unroll
        for (int kk = 0; kk < 4; kk++) {
            const int kc = kk * 8;
            uint32_t a0 = __float_as_uint(Ps[warp][g][kc + tg]);
            uint32_t a1 = __float_as_uint(Ps[warp][g + 8][kc + tg]);
            uint32_t a2 = __float_as_uint(Ps[warp][g][kc + tg + 4]);
            uint32_t a3 = __float_as_uint(Ps[warp][g + 8][kc + tg + 4]);
#pragma unroll
            for (int dt = 0; dt < 8; dt++) {
                uint32_t b0 = __float_as_uint(Vs[buf][kc + tg][dt * 8 + g]) + 0x1000u;
                uint32_t b1 = __float_as_uint(Vs[buf][kc + tg + 4][dt * 8 + g]) + 0x1000u;
                mma8(oacc[dt], a0, a1, a2, a3, b0, b1);
            }
        }

        __syncthreads();
        if (kt + 2 < NT) issue(kt + 2);
    }

    // Epilogue: normalize + write merged-head output [b, s, h*64 + d]
    const float inv0 = 1.f / lrow0;
    const float inv1 = 1.f / lrow1;
    const int row0 = q0 + warp * 16 + g;
    const int row1 = row0 + 8;
    float* o0 = out + ((size_t)(b * SEQ + row0)) * DM + h * DH;
    float* o1 = out + ((size_t)(b * SEQ + row1)) * DM + h * DH;
#pragma unroll
    for (int dt = 0; dt < 8; dt++) {
        const int col = dt * 8 + 2 * tg;
        float2 v0, v1;
        v0.x = oacc[dt][0] * inv0; v0.y = oacc[dt][1] * inv0;
        v1.x = oacc[dt][2] * inv1; v1.y = oacc[dt][3] * inv1;
        *reinterpret_cast<float2*>(o0 + col) = v0;
        *reinterpret_cast<float2*>(o1 + col) = v1;
    }
}

// ---------------------------------------------------------------------------
// Launch
// ---------------------------------------------------------------------------
extern "C" void kernel_launch(void* const* d_in, const int* in_sizes, int n_in,
                              void* d_out, int out_size)
{
    const float* q  = (const float*)d_in[0];
    const float* k  = (const float*)d_in[1];
    const float* v  = (const float*)d_in[2];
    const float* Wq = (const float*)d_in[3];
    const float* bq = (const float*)d_in[4];
    const float* Wk = (const float*)d_in[5];
    const float* bk = (const float*)d_in[6];
    const float* Wv = (const float*)d_in[7];
    const float* bv = (const float*)d_in[8];
    float* out = (float*)d_out;

    float *dq, *dk, *dv;
    cudaGetSymbolAddress((void**)&dq, g_wq);
    cudaGetSymbolAddress((void**)&dk, g_wk);
    cudaGetSymbolAddress((void**)&dv, g_wv);

    dim3 pgrid(DM / 64, M_TOTAL / 128, 3);     // (12, 64, 3)
    proj_fused_kernel<<<pgrid, 256>>>(q, k, v, Wq, bq, Wk, bk, Wv, bv, dq, dk, dv);

    dim3 agrid(SEQ / 64, NH, BATCH);           // (32, 12, 4)
    flash_mma_kernel<<<agrid, 128>>>(dq, dk, dv, out);
}

// round 12
// speedup vs baseline: 1.8000x; 1.1239x over previous
#include <cuda_runtime.h>
#include <cstdint>

#define SEQ   2048
#define DM    768
#define NH    12
#define DH    64
#define BATCH 4
#define M_TOTAL (BATCH * SEQ)   // 8192

// Projection outputs: Q fp32; K pre-split packed bf16x2 hi/lo; V fp32 (RN-prebiased)
__device__ float    g_wq[BATCH * NH * SEQ * DH];
__device__ uint32_t g_wk_hi[BATCH * NH * SEQ * (DH / 2)];
__device__ uint32_t g_wk_lo[BATCH * NH * SEQ * (DH / 2)];
__device__ float    g_wv[BATCH * NH * SEQ * DH];

// ---------------------------------------------------------------------------
// Precision helpers.
// ---------------------------------------------------------------------------
__device__ __forceinline__ uint32_t rn_bits(float x) {
    return __float_as_uint(x) + 0x1000u;        // tf32 RN after HW trunc
}
__device__ __forceinline__ uint32_t pack_bf16(float e, float o) {
    uint32_t r;
    asm("cvt.rn.bf16x2.f32 %0, %1, %2;" : "=r"(r) : "f"(o), "f"(e));
    return r;
}
__device__ __forceinline__ void bf_split(float e, float o, uint32_t& h, uint32_t& l) {
    h = pack_bf16(e, o);
    float he = __uint_as_float(h << 16);
    float ho = __uint_as_float(h & 0xFFFF0000u);
    l = pack_bf16(e - he, o - ho);
}

// m16n8k8 tf32 mma
__device__ __forceinline__ void mma8(float* c,
                                     uint32_t a0, uint32_t a1, uint32_t a2, uint32_t a3,
                                     uint32_t b0, uint32_t b1) {
    asm volatile(
        "mma.sync.aligned.m16n8k8.row.col.f32.tf32.tf32.f32 "
        "{%0,%1,%2,%3}, {%4,%5,%6,%7}, {%8,%9}, {%0,%1,%2,%3};\n"
        : "+f"(c[0]), "+f"(c[1]), "+f"(c[2]), "+f"(c[3])
        : "r"(a0), "r"(a1), "r"(a2), "r"(a3), "r"(b0), "r"(b1));
}
// m16n8k16 bf16 mma
__device__ __forceinline__ void mma16(float* c,
                                      uint32_t a0, uint32_t a1, uint32_t a2, uint32_t a3,
                                      uint32_t b0, uint32_t b1) {
    asm volatile(
        "mma.sync.aligned.m16n8k16.row.col.f32.bf16.bf16.f32 "
        "{%0,%1,%2,%3}, {%4,%5,%6,%7}, {%8,%9}, {%0,%1,%2,%3};\n"
        : "+f"(c[0]), "+f"(c[1]), "+f"(c[2]), "+f"(c[3])
        : "r"(a0), "r"(a1), "r"(a2), "r"(a3), "r"(b0), "r"(b1));
}

__device__ __forceinline__ void cp16(uint32_t smem_addr, const void* gptr) {
    asm volatile("cp.async.cg.shared.global [%0], [%1], 16;\n"
                 :: "r"(smem_addr), "l"(gptr));
}
__device__ __forceinline__ void cp_commit() {
    asm volatile("cp.async.commit_group;\n");
}

// ---------------------------------------------------------------------------
// Fused projection GEMM: z in {0,1,2} selects (Q,K,V).
// K epilogue splits to packed bf16x2 hi/lo (split happens ONCE per element).
// V epilogue pre-applies tf32 RN bias. Q plain fp32.
// ---------------------------------------------------------------------------
__global__ __launch_bounds__(256) void proj_fused_kernel(
    const float* __restrict__ Xq, const float* __restrict__ Xk, const float* __restrict__ Xv,
    const float* __restrict__ Wq, const float* __restrict__ bq,
    const float* __restrict__ Wk, const float* __restrict__ bk,
    const float* __restrict__ Wv, const float* __restrict__ bv,
    float* __restrict__ Oq, uint32_t* __restrict__ Okhi, uint32_t* __restrict__ Oklo,
    float* __restrict__ Ov)
{
    const int z = blockIdx.z;
    const float* X    = (z == 0) ? Xq : (z == 1) ? Xk : Xv;
    const float* W    = (z == 0) ? Wq : (z == 1) ? Wk : Wv;
    const float* bias = (z == 0) ? bq : (z == 1) ? bk : bv;
    const bool PRECISE = (z != 2);

    __shared__ float Xs[2][128][24];
    __shared__ float Ws[2][64][24];

    const int tid  = threadIdx.x;
    const int lane = tid & 31;
    const int warp = tid >> 5;
    const int wm   = warp & 3;
    const int wn   = warp >> 2;
    const int bm   = blockIdx.y * 128;
    const int bn   = blockIdx.x * 64;

    const int g  = lane >> 2;
    const int tg = lane & 3;

    float acc[2][4][4];
#pragma unroll
    for (int i = 0; i < 2; i++)
#pragma unroll
        for (int j = 0; j < 4; j++)
#pragma unroll
            for (int r = 0; r < 4; r++) acc[i][j][r] = 0.f;

    const uint32_t xs_base = (uint32_t)__cvta_generic_to_shared(&Xs[0][0][0]);
    const uint32_t ws_base = (uint32_t)__cvta_generic_to_shared(&Ws[0][0][0]);
    const int xrow0 = tid >> 2,  xc0 = (tid & 3) * 4;
    const int wrow  = tid >> 2,  wc  = (tid & 3) * 4;

    const int NT = DM / 16;   // 48

    auto issue = [&](int kt) {
        const int k0 = kt * 16;
        const uint32_t xb = xs_base + (uint32_t)((kt & 1) * 128 * 24 * 4);
        const uint32_t wb = ws_base + (uint32_t)((kt & 1) * 64 * 24 * 4);
        cp16(xb + (uint32_t)((xrow0      ) * 24 + xc0) * 4,
             X + (size_t)(bm + xrow0) * DM + k0 + xc0);
        cp16(xb + (uint32_t)((xrow0 + 64 ) * 24 + xc0) * 4,
             X + (size_t)(bm + xrow0 + 64) * DM + k0 + xc0);
        cp16(wb + (uint32_t)(wrow * 24 + wc) * 4,
             W + (size_t)(bn + wrow) * DM + k0 + wc);
        cp_commit();
    };

    issue(0);
    issue(1);

    for (int kt = 0; kt < NT; kt++) {
        if (kt + 1 < NT) asm volatile("cp.async.wait_group 1;\n");
        else             asm volatile("cp.async.wait_group 0;\n");
        __syncthreads();
        const int buf = kt & 1;

        if (PRECISE) {
            uint32_t ah[2][4], al[2][4], bh[4][2], bl[4][2];
#pragma unroll
            for (int mt = 0; mt < 2; mt++) {
                const int rb = wm * 32 + mt * 16;
                float2 A0 = *reinterpret_cast<const float2*>(&Xs[buf][rb + g    ][2 * tg]);
                float2 A1 = *reinterpret_cast<const float2*>(&Xs[buf][rb + g + 8][2 * tg]);
                float2 A2 = *reinterpret_cast<const float2*>(&Xs[buf][rb + g    ][2 * tg + 8]);
                float2 A3 = *reinterpret_cast<const float2*>(&Xs[buf][rb + g + 8][2 * tg + 8]);
                bf_split(A0.x, A0.y, ah[mt][0], al[mt][0]);
                bf_split(A1.x, A1.y, ah[mt][1], al[mt][1]);
                bf_split(A2.x, A2.y, ah[mt][2], al[mt][2]);
                bf_split(A3.x, A3.y, ah[mt][3], al[mt][3]);
            }
#pragma unroll
            for (int nt = 0; nt < 4; nt++) {
                const int nb = wn * 32 + nt * 8;
                float2 B0 = *reinterpret_cast<const float2*>(&Ws[buf][nb + g][2 * tg]);
                float2 B1 = *reinterpret_cast<const float2*>(&Ws[buf][nb + g][2 * tg + 8]);
                bf_split(B0.x, B0.y, bh[nt][0], bl[nt][0]);
                bf_split(B1.x, B1.y, bh[nt][1], bl[nt][1]);
            }
#pragma unroll
            for (int mt = 0; mt < 2; mt++)
#pragma unroll
                for (int nt = 0; nt < 4; nt++) {
                    mma16(acc[mt][nt], ah[mt][0], ah[mt][1], ah[mt][2], ah[mt][3],
                          bh[nt][0], bh[nt][1]);
                    mma16(acc[mt][nt], ah[mt][0], ah[mt][1], ah[mt][2], ah[mt][3],
                          bl[nt][0], bl[nt][1]);
                    mma16(acc[mt][nt], al[mt][0], al[mt][1], al[mt][2], al[mt][3],
                          bh[nt][0], bh[nt][1]);
                }
        } else {
#pragma unroll
            for (int ks = 0; ks < 2; ks++) {
                const int kk = ks * 8;
                uint32_t ah[2][4], bh[4][2];
#pragma unroll
                for (int mt = 0; mt < 2; mt++) {
                    const int rb = wm * 32 + mt * 16;
                    ah[mt][0] = rn_bits(Xs[buf][rb + g    ][kk + tg]);
                    ah[mt][1] = rn_bits(Xs[buf][rb + g + 8][kk + tg]);
                    ah[mt][2] = rn_bits(Xs[buf][rb + g    ][kk + tg + 4]);
                    ah[mt][3] = rn_bits(Xs[buf][rb + g + 8][kk + tg + 4]);
                }
#pragma unroll
                for (int nt = 0; nt < 4; nt++) {
                    const int nb = wn * 32 + nt * 8;
                    bh[nt][0] = rn_bits(Ws[buf][nb + g][kk + tg]);
                    bh[nt][1] = rn_bits(Ws[buf][nb + g][kk + tg + 4]);
                }
#pragma unroll
                for (int mt = 0; mt < 2; mt++)
#pragma unroll
                    for (int nt = 0; nt < 4; nt++)
                        mma8(acc[mt][nt], ah[mt][0], ah[mt][1], ah[mt][2], ah[mt][3],
                             bh[nt][0], bh[nt][1]);
            }
        }
        __syncthreads();
        if (kt + 2 < NT) issue(kt + 2);
    }

    // Epilogue: add bias; scatter head-split. K -> packed bf16x2 hi/lo;
    // V -> RN-prebiased fp32; Q -> fp32.
#pragma unroll
    for (int mt = 0; mt < 2; mt++) {
#pragma unroll
        for (int nt = 0; nt < 4; nt++) {
            const int n  = bn + wn * 32 + nt * 8 + 2 * tg;
            const int h  = n / DH;
            const int d  = n % DH;
            const float b0 = bias[n];
            const float b1 = bias[n + 1];
#pragma unroll
            for (int rr = 0; rr < 2; rr++) {
                const int m = bm + wm * 32 + mt * 16 + g + rr * 8;
                const int bb = m / SEQ;
                const int s  = m % SEQ;
                const float vx = acc[mt][nt][rr * 2 + 0] + b0;
                const float vy = acc[mt][nt][rr * 2 + 1] + b1;
                if (z == 1) {
                    uint32_t hi, lo;
                    bf_split(vx, vy, hi, lo);
                    const size_t off =
                        (((size_t)(bb * NH + h)) * SEQ + s) * (DH / 2) + (d >> 1);
                    Okhi[off] = hi;
                    Oklo[off] = lo;
                } else if (z == 2) {
                    uint2 v = make_uint2(rn_bits(vx), rn_bits(vy));
                    *reinterpret_cast<uint2*>(
                        Ov + (((size_t)(bb * NH + h)) * SEQ + s) * DH + d) = v;
                } else {
                    float2 v = make_float2(vx, vy);
                    *reinterpret_cast<float2*>(
                        Oq + (((size_t)(bb * NH + h)) * SEQ + s) * DH + d) = v;
                }
            }
        }
    }
}

// ---------------------------------------------------------------------------
// Flash attention. 64 q rows/block, 4 warps, key tiles of 32, double-buffered
// cp.async of PRE-SPLIT K (packed bf16x2 hi/lo) and PRE-ROUNDED V.
// Score loop: pure LDS.32 + mma16, zero ALU. PV: pure LDS + mma8, zero ALU.
// ---------------------------------------------------------------------------
__global__ __launch_bounds__(128, 4) void flash_mma_kernel(
    const float* __restrict__ Qh,
    const uint32_t* __restrict__ KhiG,
    const uint32_t* __restrict__ KloG,
    const float* __restrict__ Vh,
    float* __restrict__ out)
{
    __shared__ uint32_t KhiS[2][32][36];  // stride 36 words: reads 4g+tg+8s conflict-free
    __shared__ uint32_t KloS[2][32][36];
    __shared__ float    Vs[2][32][72];
    __shared__ float    Ps[4][16][36];

    const int tid  = threadIdx.x;
    const int lane = tid & 31;
    const int warp = tid >> 5;
    const int g    = lane >> 2;
    const int tg   = lane & 3;

    const int b  = blockIdx.z;
    const int h  = blockIdx.y;
    const int q0 = blockIdx.x * 64;
    const size_t base  = ((size_t)(b * NH + h)) * SEQ * DH;        // fp32 arrays
    const size_t base2 = ((size_t)(b * NH + h)) * SEQ * (DH / 2);  // packed K

    const uint32_t khi_base = (uint32_t)__cvta_generic_to_shared(&KhiS[0][0][0]);
    const uint32_t klo_base = (uint32_t)__cvta_generic_to_shared(&KloS[0][0][0]);
    const uint32_t vs_base  = (uint32_t)__cvta_generic_to_shared(&Vs[0][0][0]);

    auto issue = [&](int kt) {
        const uint32_t hb = khi_base + (uint32_t)((kt & 1) * 32 * 36 * 4);
        const uint32_t lb = klo_base + (uint32_t)((kt & 1) * 32 * 36 * 4);
        const uint32_t vb = vs_base  + (uint32_t)((kt & 1) * 32 * 72 * 4);
        const uint32_t* hp = KhiG + base2 + (size_t)(kt * 32) * (DH / 2);
        const uint32_t* lp = KloG + base2 + (size_t)(kt * 32) * (DH / 2);
        const float*    vp = Vh   + base  + (size_t)(kt * 32) * DH;
        // K hi/lo: 32 rows x 32 u32 = 256 16B-chunks each -> 2 per thread
#pragma unroll
        for (int i = 0; i < 2; i++) {
            const int idx = i * 128 + tid;
            const int row = idx >> 3;
            const int c   = (idx & 7) * 4;
            cp16(hb + (uint32_t)(row * 36 + c) * 4, hp + row * 32 + c);
            cp16(lb + (uint32_t)(row * 36 + c) * 4, lp + row * 32 + c);
        }
        // V: 32 rows x 64 f = 512 chunks -> 4 per thread
#pragma unroll
        for (int i = 0; i < 4; i++) {
            const int idx = i * 128 + tid;
            const int row = idx >> 4;
            const int c   = (idx & 15) * 4;
            cp16(vb + (uint32_t)(row * 72 + c) * 4, vp + row * 64 + c);
        }
        cp_commit();
    };

    // Hoisted Q fragments (bf16 hi/lo): 4 ksteps x 4 regs each
    uint32_t qh[4][4], ql[4][4];
    {
        const float* q0p = Qh + base + (size_t)(q0 + warp * 16 + g) * DH;
        const float* q1p = q0p + 8 * DH;
#pragma unroll
        for (int s = 0; s < 4; s++) {
            const int c0 = s * 16 + 2 * tg;
            float2 A0 = *reinterpret_cast<const float2*>(q0p + c0);
            float2 A1 = *reinterpret_cast<const float2*>(q1p + c0);
            float2 A2 = *reinterpret_cast<const float2*>(q0p + c0 + 8);
            float2 A3 = *reinterpret_cast<const float2*>(q1p + c0 + 8);
            bf_split(A0.x, A0.y, qh[s][0], ql[s][0]);
            bf_split(A1.x, A1.y, qh[s][1], ql[s][1]);
            bf_split(A2.x, A2.y, qh[s][2], ql[s][2]);
            bf_split(A3.x, A3.y, qh[s][3], ql[s][3]);
        }
    }

    issue(0);
    issue(1);

    float oacc[8][4];
#pragma unroll
    for (int dt = 0; dt < 8; dt++)
#pragma unroll
        for (int r = 0; r < 4; r++) oacc[dt][r] = 0.f;
    float mrow0 = -1e30f, mrow1 = -1e30f;
    float lrow0 = 0.f,    lrow1 = 0.f;

    const int NT = SEQ / 32;   // 64

    for (int kt = 0; kt < NT; kt++) {
        if (kt + 1 < NT) asm volatile("cp.async.wait_group 1;\n");
        else             asm volatile("cp.async.wait_group 0;\n");
        __syncthreads();
        const int buf = kt & 1;

        // ---- Scores: S (16 x 32) per warp, 3x bf16-k16, pure LDS+mma ----
        float sacc[4][4];
#pragma unroll
        for (int nt = 0; nt < 4; nt++)
#pragma unroll
            for (int r = 0; r < 4; r++) sacc[nt][r] = 0.f;

#pragma unroll
        for (int s = 0; s < 4; s++) {
#pragma unroll
            for (int nt = 0; nt < 4; nt++) {
                const int kr = nt * 8 + g;
                uint32_t h0 = KhiS[buf][kr][s * 8 + tg];
                uint32_t h1 = KhiS[buf][kr][s * 8 + tg + 4];
                uint32_t l0 = KloS[buf][kr][s * 8 + tg];
                uint32_t l1 = KloS[buf][kr][s * 8 + tg + 4];
                mma16(sacc[nt], qh[s][0], qh[s][1], qh[s][2], qh[s][3], h0, h1);
                mma16(sacc[nt], qh[s][0], qh[s][1], qh[s][2], qh[s][3], l0, l1);
                mma16(sacc[nt], ql[s][0], ql[s][1], ql[s][2], ql[s][3], h0, h1);
            }
        }

        // ---- Online softmax ----
        float tmax0 = sacc[0][0], tmax1 = sacc[0][2];
#pragma unroll
        for (int nt = 0; nt < 4; nt++) {
            tmax0 = fmaxf(tmax0, fmaxf(sacc[nt][0], sacc[nt][1]));
            tmax1 = fmaxf(tmax1, fmaxf(sacc[nt][2], sacc[nt][3]));
        }
        tmax0 = fmaxf(tmax0, __shfl_xor_sync(0xffffffff, tmax0, 1));
        tmax0 = fmaxf(tmax0, __shfl_xor_sync(0xffffffff, tmax0, 2));
        tmax1 = fmaxf(tmax1, __shfl_xor_sync(0xffffffff, tmax1, 1));
        tmax1 = fmaxf(tmax1, __shfl_xor_sync(0xffffffff, tmax1, 2));

        const float mnew0 = fmaxf(mrow0, tmax0);
        const float mnew1 = fmaxf(mrow1, tmax1);
        const float corr0 = __expf(mrow0 - mnew0);
        const float corr1 = __expf(mrow1 - mnew1);
        mrow0 = mnew0; mrow1 = mnew1;

        float ps0 = 0.f, ps1 = 0.f;
#pragma unroll
        for (int nt = 0; nt < 4; nt++) {
            sacc[nt][0] = __expf(sacc[nt][0] - mnew0);
            sacc[nt][1] = __expf(sacc[nt][1] - mnew0);
            sacc[nt][2] = __expf(sacc[nt][2] - mnew1);
            sacc[nt][3] = __expf(sacc[nt][3] - mnew1);
            ps0 += sacc[nt][0] + sacc[nt][1];
            ps1 += sacc[nt][2] + sacc[nt][3];
        }
        ps0 += __shfl_xor_sync(0xffffffff, ps0, 1);
        ps0 += __shfl_xor_sync(0xffffffff, ps0, 2);
        ps1 += __shfl_xor_sync(0xffffffff, ps1, 1);
        ps1 += __shfl_xor_sync(0xffffffff, ps1, 2);
        lrow0 = lrow0 * corr0 + ps0;
        lrow1 = lrow1 * corr1 + ps1;

#pragma unroll
        for (int dt = 0; dt < 8; dt++) {
            oacc[dt][0] *= corr0;
            oacc[dt][1] *= corr0;
            oacc[dt][2] *= corr1;
            oacc[dt][3] *= corr1;
        }

        // P tile to per-warp smem, pre-rounded (RN after HW trunc)
#pragma unroll
        for (int nt = 0; nt < 4; nt++) {
            const int col = nt * 8 + 2 * tg;
            *reinterpret_cast<uint2*>(&Ps[warp][g][col]) =
                make_uint2(rn_bits(sacc[nt][0]), rn_bits(sacc[nt][1]));
            *reinterpret_cast<uint2*>(&Ps[warp][g + 8][col]) =
                make_uint2(rn_bits(sacc[nt][2]), rn_bits(sacc[nt][3]));
        }
        __syncwarp();

        // ---- PV: O(16x64) += P(16x32) @ V(32x64); V already RN-prebiased ----
#pragma unroll
        for (int kk = 0; kk < 4; kk++) {
            const int kc = kk * 8;
            uint32_t a0 = __float_as_uint(Ps[warp][g][kc + tg]);
            uint32_t a1 = __float_as_uint(Ps[warp][g + 8][kc + tg]);
            uint32_t a2 = __float_as_uint(Ps[warp][g][kc + tg + 4]);
            uint32_t a3 = __float_as_uint(Ps[warp][g + 8][kc + tg + 4]);
#pragma unroll
            for (int dt = 0; dt < 8; dt++) {
                uint32_t b0 = __float_as_uint(Vs[buf][kc + tg][dt * 8 + g]);
                uint32_t b1 = __float_as_uint(Vs[buf][kc + tg + 4][dt * 8 + g]);
                mma8(oacc[dt], a0, a1, a2, a3, b0, b1);
            }
        }

        __syncthreads();
        if (kt + 2 < NT) issue(kt + 2);
    }

    // Epilogue: normalize + write merged-head output [b, s, h*64 + d]
    const float inv0 = 1.f / lrow0;
    const float inv1 = 1.f / lrow1;
    const int row0 = q0 + warp * 16 + g;
    const int row1 = row0 + 8;
    float* o0 = out + ((size_t)(b * SEQ + row0)) * DM + h * DH;
    float* o1 = out + ((size_t)(b * SEQ + row1)) * DM + h * DH;
#pragma unroll
    for (int dt = 0; dt < 8; dt++) {
        const int col = dt * 8 + 2 * tg;
        float2 v0, v1;
        v0.x = oacc[dt][0] * inv0; v0.y = oacc[dt][1] * inv0;
        v1.x = oacc[dt][2] * inv1; v1.y = oacc[dt][3] * inv1;
        *reinterpret_cast<float2*>(o0 + col) = v0;
        *reinterpret_cast<float2*>(o1 + col) = v1;
    }
}

// ---------------------------------------------------------------------------
// Launch
// ---------------------------------------------------------------------------
extern "C" void kernel_launch(void* const* d_in, const int* in_sizes, int n_in,
                              void* d_out, int out_size)
{
    const float* q  = (const float*)d_in[0];
    const float* k  = (const float*)d_in[1];
    const float* v  = (const float*)d_in[2];
    const float* Wq = (const float*)d_in[3];
    const float* bq = (const float*)d_in[4];
    const float* Wk = (const float*)d_in[5];
    const float* bk = (const float*)d_in[6];
    const float* Wv = (const float*)d_in[7];
    const float* bv = (const float*)d_in[8];
    float* out = (float*)d_out;

    float *dq, *dv;
    uint32_t *dkh, *dkl;
    cudaGetSymbolAddress((void**)&dq,  g_wq);
    cudaGetSymbolAddress((void**)&dkh, g_wk_hi);
    cudaGetSymbolAddress((void**)&dkl, g_wk_lo);
    cudaGetSymbolAddress((void**)&dv,  g_wv);

    dim3 pgrid(DM / 64, M_TOTAL / 128, 3);     // (12, 64, 3)
    proj_fused_kernel<<<pgrid, 256>>>(q, k, v, Wq, bq, Wk, bk, Wv, bv,
                                      dq, dkh, dkl, dv);

    dim3 agrid(SEQ / 64, NH, BATCH);           // (32, 12, 4)
    flash_mma_kernel<<<agrid, 128>>>(dq, dkh, dkl, dv, out);
}

// round 14
// speedup vs baseline: 1.8837x; 1.0465x over previous
#include <cuda_runtime.h>
#include <cstdint>

#define SEQ   2048
#define DM    768
#define NH    12
#define DH    64
#define BATCH 4
#define M_TOTAL (BATCH * SEQ)   // 8192

// Projection outputs:
//   Q: fp32 [b,h,s,d]
//   K: pre-split bf16x2 hi/lo, PAIRED: uint2 at (s, jj) = (word_j, word_{j+4})
//      where word_j packs dims (2j, 2j+1); jj = 4*(j/8) + (j%4), 16 uint2/row
//   V: RN-prebiased fp32, PAIRED by keys: float2 at (row p, d) = (V[s][d], V[s+4][d])
//      rows p = (s/8)*4 + (s%4)
__device__ float  g_wq[BATCH * NH * SEQ * DH];
__device__ uint2  g_wk_hi2[BATCH * NH * SEQ * 16];
__device__ uint2  g_wk_lo2[BATCH * NH * SEQ * 16];
__device__ float2 g_wv2[BATCH * NH * SEQ * (DH / 2)];

// ---------------------------------------------------------------------------
// Precision helpers.
// ---------------------------------------------------------------------------
__device__ __forceinline__ uint32_t rn_bits(float x) {
    return __float_as_uint(x) + 0x1000u;        // tf32 RN after HW trunc
}
__device__ __forceinline__ uint32_t pack_bf16(float e, float o) {
    uint32_t r;
    asm("cvt.rn.bf16x2.f32 %0, %1, %2;" : "=r"(r) : "f"(o), "f"(e));
    return r;
}
__device__ __forceinline__ void bf_split(float e, float o, uint32_t& h, uint32_t& l) {
    h = pack_bf16(e, o);
    float he = __uint_as_float(h << 16);
    float ho = __uint_as_float(h & 0xFFFF0000u);
    l = pack_bf16(e - he, o - ho);
}

// m16n8k8 tf32 mma
__device__ __forceinline__ void mma8(float* c,
                                     uint32_t a0, uint32_t a1, uint32_t a2, uint32_t a3,
                                     uint32_t b0, uint32_t b1) {
    asm volatile(
        "mma.sync.aligned.m16n8k8.row.col.f32.tf32.tf32.f32 "
        "{%0,%1,%2,%3}, {%4,%5,%6,%7}, {%8,%9}, {%0,%1,%2,%3};\n"
        : "+f"(c[0]), "+f"(c[1]), "+f"(c[2]), "+f"(c[3])
        : "r"(a0), "r"(a1), "r"(a2), "r"(a3), "r"(b0), "r"(b1));
}
// m16n8k16 bf16 mma
__device__ __forceinline__ void mma16(float* c,
                                      uint32_t a0, uint32_t a1, uint32_t a2, uint32_t a3,
                                      uint32_t b0, uint32_t b1) {
    asm volatile(
        "mma.sync.aligned.m16n8k16.row.col.f32.bf16.bf16.f32 "
        "{%0,%1,%2,%3}, {%4,%5,%6,%7}, {%8,%9}, {%0,%1,%2,%3};\n"
        : "+f"(c[0]), "+f"(c[1]), "+f"(c[2]), "+f"(c[3])
        : "r"(a0), "r"(a1), "r"(a2), "r"(a3), "r"(b0), "r"(b1));
}

__device__ __forceinline__ void cp16(uint32_t smem_addr, const void* gptr) {
    asm volatile("cp.async.cg.shared.global [%0], [%1], 16;\n"
                 :: "r"(smem_addr), "l"(gptr));
}
__device__ __forceinline__ void cp_commit() {
    asm volatile("cp.async.commit_group;\n");
}

// ---------------------------------------------------------------------------
// Fused projection GEMM: z in {0,1,2} selects (Q,K,V).
// K epilogue: bf16x2 hi/lo, paired (j, j+4) via nt/nt+1 (same thread).
// V epilogue: RN-prebias, paired (s, s+4) via shfl_xor(16).
// ---------------------------------------------------------------------------
__global__ __launch_bounds__(256) void proj_fused_kernel(
    const float* __restrict__ Xq, const float* __restrict__ Xk, const float* __restrict__ Xv,
    const float* __restrict__ Wq, const float* __restrict__ bq,
    const float* __restrict__ Wk, const float* __restrict__ bk,
    const float* __restrict__ Wv, const float* __restrict__ bv,
    float* __restrict__ Oq, uint2* __restrict__ Okhi, uint2* __restrict__ Oklo,
    float2* __restrict__ Ov2)
{
    const int z = blockIdx.z;
    const float* X    = (z == 0) ? Xq : (z == 1) ? Xk : Xv;
    const float* W    = (z == 0) ? Wq : (z == 1) ? Wk : Wv;
    const float* bias = (z == 0) ? bq : (z == 1) ? bk : bv;
    const bool PRECISE = (z != 2);

    __shared__ float Xs[2][128][24];
    __shared__ float Ws[2][64][24];

    const int tid  = threadIdx.x;
    const int lane = tid & 31;
    const int warp = tid >> 5;
    const int wm   = warp & 3;
    const int wn   = warp >> 2;
    const int bm   = blockIdx.y * 128;
    const int bn   = blockIdx.x * 64;

    const int g  = lane >> 2;
    const int tg = lane & 3;

    float acc[2][4][4];
#pragma unroll
    for (int i = 0; i < 2; i++)
#pragma unroll
        for (int j = 0; j < 4; j++)
#pragma unroll
            for (int r = 0; r < 4; r++) acc[i][j][r] = 0.f;

    const uint32_t xs_base = (uint32_t)__cvta_generic_to_shared(&Xs[0][0][0]);
    const uint32_t ws_base = (uint32_t)__cvta_generic_to_shared(&Ws[0][0][0]);
    const int xrow0 = tid >> 2,  xc0 = (tid & 3) * 4;
    const int wrow  = tid >> 2,  wc  = (tid & 3) * 4;

    const int NT = DM / 16;   // 48

    auto issue = [&](int kt) {
        const int k0 = kt * 16;
        const uint32_t xb = xs_base + (uint32_t)((kt & 1) * 128 * 24 * 4);
        const uint32_t wb = ws_base + (uint32_t)((kt & 1) * 64 * 24 * 4);
        cp16(xb + (uint32_t)((xrow0      ) * 24 + xc0) * 4,
             X + (size_t)(bm + xrow0) * DM + k0 + xc0);
        cp16(xb + (uint32_t)((xrow0 + 64 ) * 24 + xc0) * 4,
             X + (size_t)(bm + xrow0 + 64) * DM + k0 + xc0);
        cp16(wb + (uint32_t)(wrow * 24 + wc) * 4,
             W + (size_t)(bn + wrow) * DM + k0 + wc);
        cp_commit();
    };

    issue(0);
    issue(1);

    for (int kt = 0; kt < NT; kt++) {
        if (kt + 1 < NT) asm volatile("cp.async.wait_group 1;\n");
        else             asm volatile("cp.async.wait_group 0;\n");
        __syncthreads();
        const int buf = kt & 1;

        if (PRECISE) {
            uint32_t ah[2][4], al[2][4], bh[4][2], bl[4][2];
#pragma unroll
            for (int mt = 0; mt < 2; mt++) {
                const int rb = wm * 32 + mt * 16;
                float2 A0 = *reinterpret_cast<const float2*>(&Xs[buf][rb + g    ][2 * tg]);
                float2 A1 = *reinterpret_cast<const float2*>(&Xs[buf][rb + g + 8][2 * tg]);
                float2 A2 = *reinterpret_cast<const float2*>(&Xs[buf][rb + g    ][2 * tg + 8]);
                float2 A3 = *reinterpret_cast<const float2*>(&Xs[buf][rb + g + 8][2 * tg + 8]);
                bf_split(A0.x, A0.y, ah[mt][0], al[mt][0]);
                bf_split(A1.x, A1.y, ah[mt][1], al[mt][1]);
                bf_split(A2.x, A2.y, ah[mt][2], al[mt][2]);
                bf_split(A3.x, A3.y, ah[mt][3], al[mt][3]);
            }
#pragma unroll
            for (int nt = 0; nt < 4; nt++) {
                const int nb = wn * 32 + nt * 8;
                float2 B0 = *reinterpret_cast<const float2*>(&Ws[buf][nb + g][2 * tg]);
                float2 B1 = *reinterpret_cast<const float2*>(&Ws[buf][nb + g][2 * tg + 8]);
                bf_split(B0.x, B0.y, bh[nt][0], bl[nt][0]);
                bf_split(B1.x, B1.y, bh[nt][1], bl[nt][1]);
            }
#pragma unroll
            for (int mt = 0; mt < 2; mt++)
#pragma unroll
                for (int nt = 0; nt < 4; nt++) {
                    mma16(acc[mt][nt], ah[mt][0], ah[mt][1], ah[mt][2], ah[mt][3],
                          bh[nt][0], bh[nt][1]);
                    mma16(acc[mt][nt], ah[mt][0], ah[mt][1], ah[mt][2], ah[mt][3],
                          bl[nt][0], bl[nt][1]);
                    mma16(acc[mt][nt], al[mt][0], al[mt][1], al[mt][2], al[mt][3],
                          bh[nt][0], bh[nt][1]);
                }
        } else {
#pragma unroll
            for (int ks = 0; ks < 2; ks++) {
                const int kk = ks * 8;
                uint32_t ah[2][4], bh[4][2];
#pragma unroll
                for (int mt = 0; mt < 2; mt++) {
                    const int rb = wm * 32 + mt * 16;
                    ah[mt][0] = rn_bits(Xs[buf][rb + g    ][kk + tg]);
                    ah[mt][1] = rn_bits(Xs[buf][rb + g + 8][kk + tg]);
                    ah[mt][2] = rn_bits(Xs[buf][rb + g    ][kk + tg + 4]);
                    ah[mt][3] = rn_bits(Xs[buf][rb + g + 8][kk + tg + 4]);
                }
#pragma unroll
                for (int nt = 0; nt < 4; nt++) {
                    const int nb = wn * 32 + nt * 8;
                    bh[nt][0] = rn_bits(Ws[buf][nb + g][kk + tg]);
                    bh[nt][1] = rn_bits(Ws[buf][nb + g][kk + tg + 4]);
                }
#pragma unroll
                for (int mt = 0; mt < 2; mt++)
#pragma unroll
                    for (int nt = 0; nt < 4; nt++)
                        mma8(acc[mt][nt], ah[mt][0], ah[mt][1], ah[mt][2], ah[mt][3],
                             bh[nt][0], bh[nt][1]);
            }
        }
        __syncthreads();
        if (kt + 2 < NT) issue(kt + 2);
    }

    // ------------------------- Epilogues -------------------------
    const int hh = bn >> 6;   // head index (bn multiple of 64; wn*32+nt*8+2tg < 64)

    if (z == 1) {
        // K: paired uint2 (word_j from nt=2p, word_{j+4} from nt=2p+1)
#pragma unroll
        for (int mt = 0; mt < 2; mt++) {
#pragma unroll
            for (int p = 0; p < 2; p++) {
                const int nt0 = 2 * p, nt1 = nt0 + 1;
                const int n0 = bn + wn * 32 + nt0 * 8 + 2 * tg;
                const int n1 = n0 + 8;
                const float b00 = bias[n0], b01 = bias[n0 + 1];
                const float b10 = bias[n1], b11 = bias[n1 + 1];
                const int jj = 8 * wn + 4 * p + tg;     // 0..15
#pragma unroll
                for (int rr = 0; rr < 2; rr++) {
                    const int m  = bm + wm * 32 + mt * 16 + g + rr * 8;
                    const int bb = m / SEQ;
                    const int s  = m % SEQ;
                    uint32_t h0, l0, h1, l1;
                    bf_split(acc[mt][nt0][rr * 2] + b00,
                             acc[mt][nt0][rr * 2 + 1] + b01, h0, l0);
                    bf_split(acc[mt][nt1][rr * 2] + b10,
                             acc[mt][nt1][rr * 2 + 1] + b11, h1, l1);
                    const size_t off =
                        ((size_t)(bb * NH + hh) * SEQ + s) * 16 + jj;
                    Okhi[off] = make_uint2(h0, h1);
                    Oklo[off] = make_uint2(l0, l1);
                }
            }
        }
    } else if (z == 2) {
        // V: RN-prebias, pair keys (s, s+4) via shfl_xor(16)
#pragma unroll
        for (int mt = 0; mt < 2; mt++) {
#pragma unroll
            for (int nt = 0; nt < 4; nt++) {
                const int n = bn + wn * 32 + nt * 8 + 2 * tg;
                const int d = n - hh * 64;
                const float b0 = bias[n];
                const float b1 = bias[n + 1];
#pragma unroll
                for (int rr = 0; rr < 2; rr++) {
                    const int m  = bm + wm * 32 + mt * 16 + g + rr * 8;
                    const int bb = m / SEQ;
                    const int s  = m % SEQ;
                    const float fx = __uint_as_float(rn_bits(acc[mt][nt][rr * 2] + b0));
                    const float fy = __uint_as_float(rn_bits(acc[mt][nt][rr * 2 + 1] + b1));
                    const float px = __shfl_xor_sync(0xffffffff, fx, 16);
                    const float py = __shfl_xor_sync(0xffffffff, fy, 16);
                    if (g < 4) {
                        const size_t rbase =
                            (((size_t)(bb * NH + hh) * (SEQ / 8) + (s >> 3)) * 4 + g)
                            * (size_t)DH;
                        Ov2[rbase + d]     = make_float2(fx, px);
                        Ov2[rbase + d + 1] = make_float2(fy, py);
                    }
                }
            }
        }
    } else {
        // Q: plain fp32
#pragma unroll
        for (int mt = 0; mt < 2; mt++) {
#pragma unroll
            for (int nt = 0; nt < 4; nt++) {
                const int n = bn + wn * 32 + nt * 8 + 2 * tg;
                const int d = n - hh * 64;
                const float b0 = bias[n];
                const float b1 = bias[n + 1];
#pragma unroll
                for (int rr = 0; rr < 2; rr++) {
                    const int m  = bm + wm * 32 + mt * 16 + g + rr * 8;
                    const int bb = m / SEQ;
                    const int s  = m % SEQ;
                    float2 v = make_float2(acc[mt][nt][rr * 2] + b0,
                                           acc[mt][nt][rr * 2 + 1] + b1);
                    *reinterpret_cast<float2*>(
                        Oq + (((size_t)(bb * NH + hh)) * SEQ + s) * DH + d) = v;
                }
            }
        }
    }
}

// ---------------------------------------------------------------------------
// Flash attention. 64 q rows/block, 4 warps, key tiles of 32, double-buffered
// cp.async of PAIRED pre-split K (uint2 hi/lo) and PAIRED pre-rounded V
// (float2). Hot loops: LDS.64 only, zero ALU.
//   K smem row stride 20 uint2 (40 words): read lanes 8g+2tg -> conflict-free.
//   V smem row stride 68 float2 (136 words): read lanes 8tg+2g -> conflict-free.
// ---------------------------------------------------------------------------
__global__ __launch_bounds__(128, 4) void flash_mma_kernel(
    const float* __restrict__ Qh,
    const uint2* __restrict__ KhiG,
    const uint2* __restrict__ KloG,
    const float2* __restrict__ VzG,
    float* __restrict__ out)
{
    __shared__ uint2  KhiS[2][32][20];
    __shared__ uint2  KloS[2][32][20];
    __shared__ float2 VzS[2][16][68];
    __shared__ float  Ps[4][16][36];

    const int tid  = threadIdx.x;
    const int lane = tid & 31;
    const int warp = tid >> 5;
    const int g    = lane >> 2;
    const int tg   = lane & 3;

    const int b  = blockIdx.z;
    const int h  = blockIdx.y;
    const int q0 = blockIdx.x * 64;
    const size_t baseq = ((size_t)(b * NH + h)) * SEQ * DH;       // Q fp32
    const size_t basek = ((size_t)(b * NH + h)) * SEQ * 16;       // K uint2
    const size_t basev = ((size_t)(b * NH + h)) * SEQ * (DH / 16); // V float2 rows*64: SEQ/8*4*64 = SEQ*32

    const uint32_t khi_base = (uint32_t)__cvta_generic_to_shared(&KhiS[0][0][0]);
    const uint32_t klo_base = (uint32_t)__cvta_generic_to_shared(&KloS[0][0][0]);
    const uint32_t vs_base  = (uint32_t)__cvta_generic_to_shared(&VzS[0][0][0]);

    auto issue = [&](int kt) {
        const uint32_t hb = khi_base + (uint32_t)((kt & 1) * 32 * 20 * 8);
        const uint32_t lb = klo_base + (uint32_t)((kt & 1) * 32 * 20 * 8);
        const uint32_t vb = vs_base  + (uint32_t)((kt & 1) * 16 * 68 * 8);
        const uint2*  hp = KhiG + basek + (size_t)kt * 32 * 16;
        const uint2*  lp = KloG + basek + (size_t)kt * 32 * 16;
        const float2* vp = VzG + (size_t)(b * NH + h) * SEQ * 32 + (size_t)kt * 16 * 64;
        // K hi/lo: 32 rows x 16 uint2 = 256 16B chunks each -> 2 per thread
#pragma unroll
        for (int i = 0; i < 2; i++) {
            const int idx = i * 128 + tid;
            const int row = idx >> 3;
            const int c   = (idx & 7) * 2;        // uint2 units
            cp16(hb + (uint32_t)(row * 20 + c) * 8, hp + row * 16 + c);
            cp16(lb + (uint32_t)(row * 20 + c) * 8, lp + row * 16 + c);
        }
        // V: 16 rows x 64 float2 = 512 16B chunks -> 4 per thread
#pragma unroll
        for (int i = 0; i < 4; i++) {
            const int idx = i * 128 + tid;
            const int row = idx >> 5;
            const int c   = idx & 31;             // 16B chunk in row
            cp16(vb + (uint32_t)(row * 68 + c * 2) * 8, vp + row * 64 + c * 2);
        }
        cp_commit();
    };
    (void)basev;

    // Hoisted Q fragments (bf16 hi/lo): 4 ksteps x 4 regs each
    uint32_t qh[4][4], ql[4][4];
    {
        const float* q0p = Qh + baseq + (size_t)(q0 + warp * 16 + g) * DH;
        const float* q1p = q0p + 8 * DH;
#pragma unroll
        for (int s = 0; s < 4; s++) {
            const int c0 = s * 16 + 2 * tg;
            float2 A0 = *reinterpret_cast<const float2*>(q0p + c0);
            float2 A1 = *reinterpret_cast<const float2*>(q1p + c0);
            float2 A2 = *reinterpret_cast<const float2*>(q0p + c0 + 8);
            float2 A3 = *reinterpret_cast<const float2*>(q1p + c0 + 8);
            bf_split(A0.x, A0.y, qh[s][0], ql[s][0]);
            bf_split(A1.x, A1.y, qh[s][1], ql[s][1]);
            bf_split(A2.x, A2.y, qh[s][2], ql[s][2]);
            bf_split(A3.x, A3.y, qh[s][3], ql[s][3]);
        }
    }

    issue(0);
    issue(1);

    float oacc[8][4];
#pragma unroll
    for (int dt = 0; dt < 8; dt++)
#pragma unroll
        for (int r = 0; r < 4; r++) oacc[dt][r] = 0.f;
    float mrow0 = -1e30f, mrow1 = -1e30f;
    float lrow0 = 0.f,    lrow1 = 0.f;

    const int NT = SEQ / 32;   // 64

    for (int kt = 0; kt < NT; kt++) {
        if (kt + 1 < NT) asm volatile("cp.async.wait_group 1;\n");
        else             asm volatile("cp.async.wait_group 0;\n");
        __syncthreads();
        const int buf = kt & 1;

        // ---- Scores: S (16 x 32) per warp, 3x bf16-k16; 2 LDS.64 per (s,nt) ----
        float sacc[4][4];
#pragma unroll
        for (int nt = 0; nt < 4; nt++)
#pragma unroll
            for (int r = 0; r < 4; r++) sacc[nt][r] = 0.f;

#pragma unroll
        for (int s = 0; s < 4; s++) {
#pragma unroll
            for (int nt = 0; nt < 4; nt++) {
                const int kr = nt * 8 + g;
                uint2 hp2 = KhiS[buf][kr][s * 4 + tg];
                uint2 lp2 = KloS[buf][kr][s * 4 + tg];
                mma16(sacc[nt], qh[s][0], qh[s][1], qh[s][2], qh[s][3], hp2.x, hp2.y);
                mma16(sacc[nt], qh[s][0], qh[s][1], qh[s][2], qh[s][3], lp2.x, lp2.y);
                mma16(sacc[nt], ql[s][0], ql[s][1], ql[s][2], ql[s][3], hp2.x, hp2.y);
            }
        }

        // ---- Online softmax ----
        float tmax0 = sacc[0][0], tmax1 = sacc[0][2];
#pragma unroll
        for (int nt = 0; nt < 4; nt++) {
            tmax0 = fmaxf(tmax0, fmaxf(sacc[nt][0], sacc[nt][1]));
            tmax1 = fmaxf(tmax1, fmaxf(sacc[nt][2], sacc[nt][3]));
        }
        tmax0 = fmaxf(tmax0, __shfl_xor_sync(0xffffffff, tmax0, 1));
        tmax0 = fmaxf(tmax0, __shfl_xor_sync(0xffffffff, tmax0, 2));
        tmax1 = fmaxf(tmax1, __shfl_xor_sync(0xffffffff, tmax1, 1));
        tmax1 = fmaxf(tmax1, __shfl_xor_sync(0xffffffff, tmax1, 2));

        const float mnew0 = fmaxf(mrow0, tmax0);
        const float mnew1 = fmaxf(mrow1, tmax1);
        const float corr0 = __expf(mrow0 - mnew0);
        const float corr1 = __expf(mrow1 - mnew1);
        mrow0 = mnew0; mrow1 = mnew1;

        float ps0 = 0.f, ps1 = 0.f;
#pragma unroll
        for (int nt = 0; nt < 4; nt++) {
            sacc[nt][0] = __expf(sacc[nt][0] - mnew0);
            sacc[nt][1] = __expf(sacc[nt][1] - mnew0);
            sacc[nt][2] = __expf(sacc[nt][2] - mnew1);
            sacc[nt][3] = __expf(sacc[nt][3] - mnew1);
            ps0 += sacc[nt][0] + sacc[nt][1];
            ps1 += sacc[nt][2] + sacc[nt][3];
        }
        ps0 += __shfl_xor_sync(0xffffffff, ps0, 1);
        ps0 += __shfl_xor_sync(0xffffffff, ps0, 2);
        ps1 += __shfl_xor_sync(0xffffffff, ps1, 1);
        ps1 += __shfl_xor_sync(0xffffffff, ps1, 2);
        lrow0 = lrow0 * corr0 + ps0;
        lrow1 = lrow1 * corr1 + ps1;

#pragma unroll
        for (int dt = 0; dt < 8; dt++) {
            oacc[dt][0] *= corr0;
            oacc[dt][1] *= corr0;
            oacc[dt][2] *= corr1;
            oacc[dt][3] *= corr1;
        }

        // P tile to per-warp smem, pre-rounded (RN after HW trunc)
#pragma unroll
        for (int nt = 0; nt < 4; nt++) {
            const int col = nt * 8 + 2 * tg;
            *reinterpret_cast<uint2*>(&Ps[warp][g][col]) =
                make_uint2(rn_bits(sacc[nt][0]), rn_bits(sacc[nt][1]));
            *reinterpret_cast<uint2*>(&Ps[warp][g + 8][col]) =
                make_uint2(rn_bits(sacc[nt][2]), rn_bits(sacc[nt][3]));
        }
        __syncwarp();

        // ---- PV: O(16x64) += P(16x32) @ V(32x64); 1 LDS.64 per (kk,dt) ----
#pragma unroll
        for (int kk = 0; kk < 4; kk++) {
            const int kc = kk * 8;
            uint32_t a0 = __float_as_uint(Ps[warp][g][kc + tg]);
            uint32_t a1 = __float_as_uint(Ps[warp][g + 8][kc + tg]);
            uint32_t a2 = __float_as_uint(Ps[warp][g][kc + tg + 4]);
            uint32_t a3 = __float_as_uint(Ps[warp][g + 8][kc + tg + 4]);
#pragma unroll
            for (int dt = 0; dt < 8; dt++) {
                float2 vp2 = VzS[buf][kk * 4 + tg][dt * 8 + g];
                mma8(oacc[dt], a0, a1, a2, a3,
                     __float_as_uint(vp2.x), __float_as_uint(vp2.y));
            }
        }

        __syncthreads();
        if (kt + 2 < NT) issue(kt + 2);
    }

    // Epilogue: normalize + write merged-head output [b, s, h*64 + d]
    const float inv0 = 1.f / lrow0;
    const float inv1 = 1.f / lrow1;
    const int row0 = q0 + warp * 16 + g;
    const int row1 = row0 + 8;
    float* o0 = out + ((size_t)(b * SEQ + row0)) * DM + h * DH;
    float* o1 = out + ((size_t)(b * SEQ + row1)) * DM + h * DH;
#pragma unroll
    for (int dt = 0; dt < 8; dt++) {
        const int col = dt * 8 + 2 * tg;
        float2 v0, v1;
        v0.x = oacc[dt][0] * inv0; v0.y = oacc[dt][1] * inv0;
        v1.x = oacc[dt][2] * inv1; v1.y = oacc[dt][3] * inv1;
        *reinterpret_cast<float2*>(o0 + col) = v0;
        *reinterpret_cast<float2*>(o1 + col) = v1;
    }
}

// ---------------------------------------------------------------------------
// Launch
// ---------------------------------------------------------------------------
extern "C" void kernel_launch(void* const* d_in, const int* in_sizes, int n_in,
                              void* d_out, int out_size)
{
    const float* q  = (const float*)d_in[0];
    const float* k  = (const float*)d_in[1];
    const float* v  = (const float*)d_in[2];
    const float* Wq = (const float*)d_in[3];
    const float* bq = (const float*)d_in[4];
    const float* Wk = (const float*)d_in[5];
    const float* bk = (const float*)d_in[6];
    const float* Wv = (const float*)d_in[7];
    const float* bv = (const float*)d_in[8];
    float* out = (float*)d_out;

    float *dq;
    uint2 *dkh, *dkl;
    float2 *dv2;
    cudaGetSymbolAddress((void**)&dq,  g_wq);
    cudaGetSymbolAddress((void**)&dkh, g_wk_hi2);
    cudaGetSymbolAddress((void**)&dkl, g_wk_lo2);
    cudaGetSymbolAddress((void**)&dv2, g_wv2);

    dim3 pgrid(DM / 64, M_TOTAL / 128, 3);     // (12, 64, 3)
    proj_fused_kernel<<<pgrid, 256>>>(q, k, v, Wq, bq, Wk, bk, Wv, bv,
                                      dq, dkh, dkl, dv2);

    dim3 agrid(SEQ / 64, NH, BATCH);           // (32, 12, 4)
    flash_mma_kernel<<<agrid, 128>>>(dq, dkh, dkl, dv2, out);
}

// round 15
// speedup vs baseline: 1.9055x; 1.0116x over previous
#include <cuda_runtime.h>
#include <cstdint>

#define SEQ   2048
#define DM    768
#define NH    12
#define DH    64
#define BATCH 4
#define M_TOTAL (BATCH * SEQ)   // 8192

// Projection outputs:
//   Q: fp32 [b,h,s,d]
//   K: pre-split bf16x2, INTERLEAVED uint4 (h_j, h_{j+4}, l_j, l_{j+4}) at
//      (s, jj): word_j packs dims (2j,2j+1); jj = 4*(j/8) + (j%4), 16 uint4/row
//   V: RN-prebiased fp32, QUAD-PACKED float4 = (V[s],V[s+4],V[s+8],V[s+12])[d]
//      packed row R = (s/16)*4 + s%4, 64 float4 per row, SEQ/4 rows per (b,h)
__device__ float  g_wq[BATCH * NH * SEQ * DH];
__device__ uint4  g_wk_q[BATCH * NH * SEQ * 16];
__device__ float4 g_wv4[BATCH * NH * (SEQ / 4) * DH];

// ---------------------------------------------------------------------------
// Precision helpers.
// ---------------------------------------------------------------------------
__device__ __forceinline__ uint32_t rn_bits(float x) {
    return __float_as_uint(x) + 0x1000u;        // tf32 RN after HW trunc
}
__device__ __forceinline__ float rn_f(float x) {
    return __uint_as_float(__float_as_uint(x) + 0x1000u);
}
__device__ __forceinline__ uint32_t pack_bf16(float e, float o) {
    uint32_t r;
    asm("cvt.rn.bf16x2.f32 %0, %1, %2;" : "=r"(r) : "f"(o), "f"(e));
    return r;
}
__device__ __forceinline__ void bf_split(float e, float o, uint32_t& h, uint32_t& l) {
    h = pack_bf16(e, o);
    float he = __uint_as_float(h << 16);
    float ho = __uint_as_float(h & 0xFFFF0000u);
    l = pack_bf16(e - he, o - ho);
}

// m16n8k8 tf32 mma
__device__ __forceinline__ void mma8(float* c,
                                     uint32_t a0, uint32_t a1, uint32_t a2, uint32_t a3,
                                     uint32_t b0, uint32_t b1) {
    asm volatile(
        "mma.sync.aligned.m16n8k8.row.col.f32.tf32.tf32.f32 "
        "{%0,%1,%2,%3}, {%4,%5,%6,%7}, {%8,%9}, {%0,%1,%2,%3};\n"
        : "+f"(c[0]), "+f"(c[1]), "+f"(c[2]), "+f"(c[3])
        : "r"(a0), "r"(a1), "r"(a2), "r"(a3), "r"(b0), "r"(b1));
}
// m16n8k16 bf16 mma
__device__ __forceinline__ void mma16(float* c,
                                      uint32_t a0, uint32_t a1, uint32_t a2, uint32_t a3,
                                      uint32_t b0, uint32_t b1) {
    asm volatile(
        "mma.sync.aligned.m16n8k16.row.col.f32.bf16.bf16.f32 "
        "{%0,%1,%2,%3}, {%4,%5,%6,%7}, {%8,%9}, {%0,%1,%2,%3};\n"
        : "+f"(c[0]), "+f"(c[1]), "+f"(c[2]), "+f"(c[3])
        : "r"(a0), "r"(a1), "r"(a2), "r"(a3), "r"(b0), "r"(b1));
}

__device__ __forceinline__ void cp16(uint32_t smem_addr, const void* gptr) {
    asm volatile("cp.async.cg.shared.global [%0], [%1], 16;\n"
                 :: "r"(smem_addr), "l"(gptr));
}
__device__ __forceinline__ void cp_commit() {
    asm volatile("cp.async.commit_group;\n");
}

// ---------------------------------------------------------------------------
// Fused projection GEMM: z in {0,1,2} selects (Q,K,V).
// ---------------------------------------------------------------------------
__global__ __launch_bounds__(256) void proj_fused_kernel(
    const float* __restrict__ Xq, const float* __restrict__ Xk, const float* __restrict__ Xv,
    const float* __restrict__ Wq, const float* __restrict__ bq,
    const float* __restrict__ Wk, const float* __restrict__ bk,
    const float* __restrict__ Wv, const float* __restrict__ bv,
    float* __restrict__ Oq, uint4* __restrict__ Okq, float4* __restrict__ Ov4)
{
    const int z = blockIdx.z;
    const float* X    = (z == 0) ? Xq : (z == 1) ? Xk : Xv;
    const float* W    = (z == 0) ? Wq : (z == 1) ? Wk : Wv;
    const float* bias = (z == 0) ? bq : (z == 1) ? bk : bv;
    const bool PRECISE = (z != 2);

    __shared__ float Xs[2][128][24];
    __shared__ float Ws[2][64][24];

    const int tid  = threadIdx.x;
    const int lane = tid & 31;
    const int warp = tid >> 5;
    const int wm   = warp & 3;
    const int wn   = warp >> 2;
    const int bm   = blockIdx.y * 128;
    const int bn   = blockIdx.x * 64;

    const int g  = lane >> 2;
    const int tg = lane & 3;

    float acc[2][4][4];
#pragma unroll
    for (int i = 0; i < 2; i++)
#pragma unroll
        for (int j = 0; j < 4; j++)
#pragma unroll
            for (int r = 0; r < 4; r++) acc[i][j][r] = 0.f;

    const uint32_t xs_base = (uint32_t)__cvta_generic_to_shared(&Xs[0][0][0]);
    const uint32_t ws_base = (uint32_t)__cvta_generic_to_shared(&Ws[0][0][0]);
    const int xrow0 = tid >> 2,  xc0 = (tid & 3) * 4;
    const int wrow  = tid >> 2,  wc  = (tid & 3) * 4;

    const int NT = DM / 16;   // 48

    auto issue = [&](int kt) {
        const int k0 = kt * 16;
        const uint32_t xb = xs_base + (uint32_t)((kt & 1) * 128 * 24 * 4);
        const uint32_t wb = ws_base + (uint32_t)((kt & 1) * 64 * 24 * 4);
        cp16(xb + (uint32_t)((xrow0      ) * 24 + xc0) * 4,
             X + (size_t)(bm + xrow0) * DM + k0 + xc0);
        cp16(xb + (uint32_t)((xrow0 + 64 ) * 24 + xc0) * 4,
             X + (size_t)(bm + xrow0 + 64) * DM + k0 + xc0);
        cp16(wb + (uint32_t)(wrow * 24 + wc) * 4,
             W + (size_t)(bn + wrow) * DM + k0 + wc);
        cp_commit();
    };

    issue(0);
    issue(1);

    for (int kt = 0; kt < NT; kt++) {
        if (kt + 1 < NT) asm volatile("cp.async.wait_group 1;\n");
        else             asm volatile("cp.async.wait_group 0;\n");
        __syncthreads();
        const int buf = kt & 1;

        if (PRECISE) {
            uint32_t ah[2][4], al[2][4], bh[4][2], bl[4][2];
#pragma unroll
            for (int mt = 0; mt < 2; mt++) {
                const int rb = wm * 32 + mt * 16;
                float2 A0 = *reinterpret_cast<const float2*>(&Xs[buf][rb + g    ][2 * tg]);
                float2 A1 = *reinterpret_cast<const float2*>(&Xs[buf][rb + g + 8][2 * tg]);
                float2 A2 = *reinterpret_cast<const float2*>(&Xs[buf][rb + g    ][2 * tg + 8]);
                float2 A3 = *reinterpret_cast<const float2*>(&Xs[buf][rb + g + 8][2 * tg + 8]);
                bf_split(A0.x, A0.y, ah[mt][0], al[mt][0]);
                bf_split(A1.x, A1.y, ah[mt][1], al[mt][1]);
                bf_split(A2.x, A2.y, ah[mt][2], al[mt][2]);
                bf_split(A3.x, A3.y, ah[mt][3], al[mt][3]);
            }
#pragma unroll
            for (int nt = 0; nt < 4; nt++) {
                const int nb = wn * 32 + nt * 8;
                float2 B0 = *reinterpret_cast<const float2*>(&Ws[buf][nb + g][2 * tg]);
                float2 B1 = *reinterpret_cast<const float2*>(&Ws[buf][nb + g][2 * tg + 8]);
                bf_split(B0.x, B0.y, bh[nt][0], bl[nt][0]);
                bf_split(B1.x, B1.y, bh[nt][1], bl[nt][1]);
            }
#pragma unroll
            for (int mt = 0; mt < 2; mt++)
#pragma unroll
                for (int nt = 0; nt < 4; nt++) {
                    mma16(acc[mt][nt], ah[mt][0], ah[mt][1], ah[mt][2], ah[mt][3],
                          bh[nt][0], bh[nt][1]);
                    mma16(acc[mt][nt], ah[mt][0], ah[mt][1], ah[mt][2], ah[mt][3],
                          bl[nt][0], bl[nt][1]);
                    mma16(acc[mt][nt], al[mt][0], al[mt][1], al[mt][2], al[mt][3],
                          bh[nt][0], bh[nt][1]);
                }
        } else {
#pragma unroll
            for (int ks = 0; ks < 2; ks++) {
                const int kk = ks * 8;
                uint32_t ah[2][4], bh[4][2];
#pragma unroll
                for (int mt = 0; mt < 2; mt++) {
                    const int rb = wm * 32 + mt * 16;
                    ah[mt][0] = rn_bits(Xs[buf][rb + g    ][kk + tg]);
                    ah[mt][1] = rn_bits(Xs[buf][rb + g + 8][kk + tg]);
                    ah[mt][2] = rn_bits(Xs[buf][rb + g    ][kk + tg + 4]);
                    ah[mt][3] = rn_bits(Xs[buf][rb + g + 8][kk + tg + 4]);
                }
#pragma unroll
                for (int nt = 0; nt < 4; nt++) {
                    const int nb = wn * 32 + nt * 8;
                    bh[nt][0] = rn_bits(Ws[buf][nb + g][kk + tg]);
                    bh[nt][1] = rn_bits(Ws[buf][nb + g][kk + tg + 4]);
                }
#pragma unroll
                for (int mt = 0; mt < 2; mt++)
#pragma unroll
                    for (int nt = 0; nt < 4; nt++)
                        mma8(acc[mt][nt], ah[mt][0], ah[mt][1], ah[mt][2], ah[mt][3],
                             bh[nt][0], bh[nt][1]);
            }
        }
        __syncthreads();
        if (kt + 2 < NT) issue(kt + 2);
    }

    // ------------------------- Epilogues -------------------------
    const int hh = bn >> 6;   // head index

    if (z == 1) {
        // K: interleaved uint4 (h_j, h_{j+4}, l_j, l_{j+4})
#pragma unroll
        for (int mt = 0; mt < 2; mt++) {
#pragma unroll
            for (int p = 0; p < 2; p++) {
                const int nt0 = 2 * p, nt1 = nt0 + 1;
                const int n0 = bn + wn * 32 + nt0 * 8 + 2 * tg;
                const int n1 = n0 + 8;
                const float b00 = bias[n0], b01 = bias[n0 + 1];
                const float b10 = bias[n1], b11 = bias[n1 + 1];
                const int jj = 8 * wn + 4 * p + tg;     // 0..15
#pragma unroll
                for (int rr = 0; rr < 2; rr++) {
                    const int m  = bm + wm * 32 + mt * 16 + g + rr * 8;
                    const int bb = m / SEQ;
                    const int s  = m % SEQ;
                    uint32_t h0, l0, h1, l1;
                    bf_split(acc[mt][nt0][rr * 2] + b00,
                             acc[mt][nt0][rr * 2 + 1] + b01, h0, l0);
                    bf_split(acc[mt][nt1][rr * 2] + b10,
                             acc[mt][nt1][rr * 2 + 1] + b11, h1, l1);
                    const size_t off =
                        ((size_t)(bb * NH + hh) * SEQ + s) * 16 + jj;
                    Okq[off] = make_uint4(h0, h1, l0, l1);
                }
            }
        }
    } else if (z == 2) {
        // V: RN-prebias, quad-pack rows (s, s+4, s+8, s+12)
#pragma unroll
        for (int mt = 0; mt < 2; mt++) {
#pragma unroll
            for (int nt = 0; nt < 4; nt++) {
                const int n = bn + wn * 32 + nt * 8 + 2 * tg;
                const int d = n - hh * 64;
                const float b0 = bias[n];
                const float b1 = bias[n + 1];
                const float fx0 = rn_f(acc[mt][nt][0] + b0);
                const float fy0 = rn_f(acc[mt][nt][1] + b1);
                const float fx1 = rn_f(acc[mt][nt][2] + b0);
                const float fy1 = rn_f(acc[mt][nt][3] + b1);
                const float px0 = __shfl_xor_sync(0xffffffff, fx0, 16);
                const float py0 = __shfl_xor_sync(0xffffffff, fy0, 16);
                const float px1 = __shfl_xor_sync(0xffffffff, fx1, 16);
                const float py1 = __shfl_xor_sync(0xffffffff, fy1, 16);
                if (g < 4) {
                    const int m0 = bm + wm * 32 + mt * 16 + g;   // component-0 row
                    const int bb = m0 / SEQ;
                    const int s0 = m0 % SEQ;
                    const size_t R = (size_t)(bb * NH + hh) * (SEQ / 4)
                                   + (s0 >> 4) * 4 + g;
                    Ov4[R * DH + d]     = make_float4(fx0, px0, fx1, px1);
                    Ov4[R * DH + d + 1] = make_float4(fy0, py0, fy1, py1);
                }
            }
        }
    } else {
        // Q: plain fp32
#pragma unroll
        for (int mt = 0; mt < 2; mt++) {
#pragma unroll
            for (int nt = 0; nt < 4; nt++) {
                const int n = bn + wn * 32 + nt * 8 + 2 * tg;
                const int d = n - hh * 64;
                const float b0 = bias[n];
                const float b1 = bias[n + 1];
#pragma unroll
                for (int rr = 0; rr < 2; rr++) {
                    const int m  = bm + wm * 32 + mt * 16 + g + rr * 8;
                    const int bb = m / SEQ;
                    const int s  = m % SEQ;
                    float2 v = make_float2(acc[mt][nt][rr * 2] + b0,
                                           acc[mt][nt][rr * 2 + 1] + b1);
                    *reinterpret_cast<float2*>(
                        Oq + (((size_t)(bb * NH + hh)) * SEQ + s) * DH + d) = v;
                }
            }
        }
    }
}

// ---------------------------------------------------------------------------
// Flash attention. Hot loops are LDS.128-only:
//   K: uint4 (hi0,hi1,lo0,lo1), smem stride 20 uint4 -> (4g+tg) mod 8 distinct.
//   V: float4 quad rows,      smem stride 66 float4 -> (2tg+g) mod 8 distinct.
// ---------------------------------------------------------------------------
__global__ __launch_bounds__(128, 4) void flash_mma_kernel(
    const float* __restrict__ Qh,
    const uint4* __restrict__ KqG,
    const float4* __restrict__ VqG,
    float* __restrict__ out)
{
    __shared__ uint4  KqS[2][32][20];     // 20480 B
    __shared__ float4 VqS[2][8][66];      // 16896 B
    __shared__ float  Ps[4][16][36];      //  9216 B   (total 45.5 KB)

    const int tid  = threadIdx.x;
    const int lane = tid & 31;
    const int warp = tid >> 5;
    const int g    = lane >> 2;
    const int tg   = lane & 3;

    const int b  = blockIdx.z;
    const int h  = blockIdx.y;
    const int q0 = blockIdx.x * 64;
    const size_t baseq = ((size_t)(b * NH + h)) * SEQ * DH;         // Q fp32
    const size_t basek = ((size_t)(b * NH + h)) * SEQ * 16;         // K uint4
    const size_t basev = ((size_t)(b * NH + h)) * (SEQ / 4) * DH;   // V float4

    const uint32_t kq_base = (uint32_t)__cvta_generic_to_shared(&KqS[0][0][0]);
    const uint32_t vq_base = (uint32_t)__cvta_generic_to_shared(&VqS[0][0][0]);

    auto issue = [&](int kt) {
        const uint32_t kb = kq_base + (uint32_t)((kt & 1) * 32 * 20 * 16);
        const uint32_t vb = vq_base + (uint32_t)((kt & 1) * 8 * 66 * 16);
        const uint4*  kp = KqG + basek + (size_t)kt * 32 * 16;
        const float4* vp = VqG + basev + (size_t)kt * 8 * DH;
        // K: 32 rows x 16 uint4 = 512 chunks -> 4 per thread
#pragma unroll
        for (int i = 0; i < 4; i++) {
            const int idx = i * 128 + tid;
            const int row = idx >> 4;
            const int c   = idx & 15;
            cp16(kb + (uint32_t)(row * 20 + c) * 16, kp + row * 16 + c);
        }
        // V: 8 rows x 64 float4 = 512 chunks -> 4 per thread
#pragma unroll
        for (int i = 0; i < 4; i++) {
            const int idx = i * 128 + tid;
            const int row = idx >> 6;
            const int c   = idx & 63;
            cp16(vb + (uint32_t)(row * 66 + c) * 16, vp + row * DH + c);
        }
        cp_commit();
    };

    // Hoisted Q fragments (bf16 hi/lo): 4 ksteps x 4 regs each
    uint32_t qh[4][4], ql[4][4];
    {
        const float* q0p = Qh + baseq + (size_t)(q0 + warp * 16 + g) * DH;
        const float* q1p = q0p + 8 * DH;
#pragma unroll
        for (int s = 0; s < 4; s++) {
            const int c0 = s * 16 + 2 * tg;
            float2 A0 = *reinterpret_cast<const float2*>(q0p + c0);
            float2 A1 = *reinterpret_cast<const float2*>(q1p + c0);
            float2 A2 = *reinterpret_cast<const float2*>(q0p + c0 + 8);
            float2 A3 = *reinterpret_cast<const float2*>(q1p + c0 + 8);
            bf_split(A0.x, A0.y, qh[s][0], ql[s][0]);
            bf_split(A1.x, A1.y, qh[s][1], ql[s][1]);
            bf_split(A2.x, A2.y, qh[s][2], ql[s][2]);
            bf_split(A3.x, A3.y, qh[s][3], ql[s][3]);
        }
    }

    issue(0);
    issue(1);

    float oacc[8][4];
#pragma unroll
    for (int dt = 0; dt < 8; dt++)
#pragma unroll
        for (int r = 0; r < 4; r++) oacc[dt][r] = 0.f;
    float mrow0 = -1e30f, mrow1 = -1e30f;
    float lrow0 = 0.f,    lrow1 = 0.f;

    const int NT = SEQ / 32;   // 64

    for (int kt = 0; kt < NT; kt++) {
        if (kt + 1 < NT) asm volatile("cp.async.wait_group 1;\n");
        else             asm volatile("cp.async.wait_group 0;\n");
        __syncthreads();
        const int buf = kt & 1;

        // ---- Scores: 1 LDS.128 + 3 mma16 per (s,nt) ----
        float sacc[4][4];
#pragma unroll
        for (int nt = 0; nt < 4; nt++)
#pragma unroll
            for (int r = 0; r < 4; r++) sacc[nt][r] = 0.f;

#pragma unroll
        for (int s = 0; s < 4; s++) {
#pragma unroll
            for (int nt = 0; nt < 4; nt++) {
                uint4 w = KqS[buf][nt * 8 + g][s * 4 + tg];
                mma16(sacc[nt], qh[s][0], qh[s][1], qh[s][2], qh[s][3], w.x, w.y);
                mma16(sacc[nt], qh[s][0], qh[s][1], qh[s][2], qh[s][3], w.z, w.w);
                mma16(sacc[nt], ql[s][0], ql[s][1], ql[s][2], ql[s][3], w.x, w.y);
            }
        }

        // ---- Online softmax ----
        float tmax0 = sacc[0][0], tmax1 = sacc[0][2];
#pragma unroll
        for (int nt = 0; nt < 4; nt++) {
            tmax0 = fmaxf(tmax0, fmaxf(sacc[nt][0], sacc[nt][1]));
            tmax1 = fmaxf(tmax1, fmaxf(sacc[nt][2], sacc[nt][3]));
        }
        tmax0 = fmaxf(tmax0, __shfl_xor_sync(0xffffffff, tmax0, 1));
        tmax0 = fmaxf(tmax0, __shfl_xor_sync(0xffffffff, tmax0, 2));
        tmax1 = fmaxf(tmax1, __shfl_xor_sync(0xffffffff, tmax1, 1));
        tmax1 = fmaxf(tmax1, __shfl_xor_sync(0xffffffff, tmax1, 2));

        const float mnew0 = fmaxf(mrow0, tmax0);
        const float mnew1 = fmaxf(mrow1, tmax1);
        const float corr0 = __expf(mrow0 - mnew0);
        const float corr1 = __expf(mrow1 - mnew1);
        mrow0 = mnew0; mrow1 = mnew1;

        float ps0 = 0.f, ps1 = 0.f;
#pragma unroll
        for (int nt = 0; nt < 4; nt++) {
            sacc[nt][0] = __expf(sacc[nt][0] - mnew0);
            sacc[nt][1] = __expf(sacc[nt][1] - mnew0);
            sacc[nt][2] = __expf(sacc[nt][2] - mnew1);
            sacc[nt][3] = __expf(sacc[nt][3] - mnew1);
            ps0 += sacc[nt][0] + sacc[nt][1];
            ps1 += sacc[nt][2] + sacc[nt][3];
        }
        ps0 += __shfl_xor_sync(0xffffffff, ps0, 1);
        ps0 += __shfl_xor_sync(0xffffffff, ps0, 2);
        ps1 += __shfl_xor_sync(0xffffffff, ps1, 1);
        ps1 += __shfl_xor_sync(0xffffffff, ps1, 2);
        lrow0 = lrow0 * corr0 + ps0;
        lrow1 = lrow1 * corr1 + ps1;

#pragma unroll
        for (int dt = 0; dt < 8; dt++) {
            oacc[dt][0] *= corr0;
            oacc[dt][1] *= corr0;
            oacc[dt][2] *= corr1;
            oacc[dt][3] *= corr1;
        }

        // P tile to per-warp smem, pre-rounded (RN after HW trunc)
#pragma unroll
        for (int nt = 0; nt < 4; nt++) {
            const int col = nt * 8 + 2 * tg;
            *reinterpret_cast<uint2*>(&Ps[warp][g][col]) =
                make_uint2(rn_bits(sacc[nt][0]), rn_bits(sacc[nt][1]));
            *reinterpret_cast<uint2*>(&Ps[warp][g + 8][col]) =
                make_uint2(rn_bits(sacc[nt][2]), rn_bits(sacc[nt][3]));
        }
        __syncwarp();

        // ---- PV: 1 LDS.128 feeds 2 mma8 per (half,dt) ----
#pragma unroll
        for (int half = 0; half < 2; half++) {
            const int kc0 = half * 16;
            const int kc1 = half * 16 + 8;
            uint32_t a00 = __float_as_uint(Ps[warp][g][kc0 + tg]);
            uint32_t a01 = __float_as_uint(Ps[warp][g + 8][kc0 + tg]);
            uint32_t a02 = __float_as_uint(Ps[warp][g][kc0 + tg + 4]);
            uint32_t a03 = __float_as_uint(Ps[warp][g + 8][kc0 + tg + 4]);
            uint32_t a10 = __float_as_uint(Ps[warp][g][kc1 + tg]);
            uint32_t a11 = __float_as_uint(Ps[warp][g + 8][kc1 + tg]);
            uint32_t a12 = __float_as_uint(Ps[warp][g][kc1 + tg + 4]);
            uint32_t a13 = __float_as_uint(Ps[warp][g + 8][kc1 + tg + 4]);
#pragma unroll
            for (int dt = 0; dt < 8; dt++) {
                float4 v4 = VqS[buf][half * 4 + tg][dt * 8 + g];
                mma8(oacc[dt], a00, a01, a02, a03,
                     __float_as_uint(v4.x), __float_as_uint(v4.y));
                mma8(oacc[dt], a10, a11, a12, a13,
                     __float_as_uint(v4.z), __float_as_uint(v4.w));
            }
        }

        __syncthreads();
        if (kt + 2 < NT) issue(kt + 2);
    }

    // Epilogue: normalize + write merged-head output [b, s, h*64 + d]
    const float inv0 = 1.f / lrow0;
    const float inv1 = 1.f / lrow1;
    const int row0 = q0 + warp * 16 + g;
    const int row1 = row0 + 8;
    float* o0 = out + ((size_t)(b * SEQ + row0)) * DM + h * DH;
    float* o1 = out + ((size_t)(b * SEQ + row1)) * DM + h * DH;
#pragma unroll
    for (int dt = 0; dt < 8; dt++) {
        const int col = dt * 8 + 2 * tg;
        float2 v0, v1;
        v0.x = oacc[dt][0] * inv0; v0.y = oacc[dt][1] * inv0;
        v1.x = oacc[dt][2] * inv1; v1.y = oacc[dt][3] * inv1;
        *reinterpret_cast<float2*>(o0 + col) = v0;
        *reinterpret_cast<float2*>(o1 + col) = v1;
    }
}

// ---------------------------------------------------------------------------
// Launch
// ---------------------------------------------------------------------------
extern "C" void kernel_launch(void* const* d_in, const int* in_sizes, int n_in,
                              void* d_out, int out_size)
{
    const float* q  = (const float*)d_in[0];
    const float* k  = (const float*)d_in[1];
    const float* v  = (const float*)d_in[2];
    const float* Wq = (const float*)d_in[3];
    const float* bq = (const float*)d_in[4];
    const float* Wk = (const float*)d_in[5];
    const float* bk = (const float*)d_in[6];
    const float* Wv = (const float*)d_in[7];
    const float* bv = (const float*)d_in[8];
    float* out = (float*)d_out;

    float  *dq;
    uint4  *dkq;
    float4 *dv4;
    cudaGetSymbolAddress((void**)&dq,  g_wq);
    cudaGetSymbolAddress((void**)&dkq, g_wk_q);
    cudaGetSymbolAddress((void**)&dv4, g_wv4);

    dim3 pgrid(DM / 64, M_TOTAL / 128, 3);     // (12, 64, 3)
    proj_fused_kernel<<<pgrid, 256>>>(q, k, v, Wq, bq, Wk, bk, Wv, bv,
                                      dq, dkq, dv4);

    dim3 agrid(SEQ / 64, NH, BATCH);           // (32, 12, 4)
    flash_mma_kernel<<<agrid, 128>>>(dq, dkq, dv4, out);
}

// round 16
// speedup vs baseline: 2.0173x; 1.0586x over previous
#include <cuda_runtime.h>
#include <cstdint>

#define SEQ   2048
#define DM    768
#define NH    12
#define DH    64
#define BATCH 4
#define M_TOTAL (BATCH * SEQ)   // 8192

// Projection outputs:
//   Q: fp32 [b,h,s,d]
//   K: pre-split bf16x2, INTERLEAVED uint4 (h_j, h_{j+4}, l_j, l_{j+4})
//   V: RN-prebiased fp32, QUAD-PACKED float4 = (V[s],V[s+4],V[s+8],V[s+12])[d]
__device__ float  g_wq[BATCH * NH * SEQ * DH];
__device__ uint4  g_wk_q[BATCH * NH * SEQ * 16];
__device__ float4 g_wv4[BATCH * NH * (SEQ / 4) * DH];

// ---------------------------------------------------------------------------
// Precision helpers.
// ---------------------------------------------------------------------------
__device__ __forceinline__ uint32_t rn_bits(float x) {
    return __float_as_uint(x) + 0x1000u;        // tf32 RN after HW trunc
}
__device__ __forceinline__ float rn_f(float x) {
    return __uint_as_float(__float_as_uint(x) + 0x1000u);
}
__device__ __forceinline__ uint32_t pack_bf16(float e, float o) {
    uint32_t r;
    asm("cvt.rn.bf16x2.f32 %0, %1, %2;" : "=r"(r) : "f"(o), "f"(e));
    return r;
}
__device__ __forceinline__ void bf_split(float e, float o, uint32_t& h, uint32_t& l) {
    h = pack_bf16(e, o);
    float he = __uint_as_float(h << 16);
    float ho = __uint_as_float(h & 0xFFFF0000u);
    l = pack_bf16(e - he, o - ho);
}

// m16n8k8 tf32 mma
__device__ __forceinline__ void mma8(float* c,
                                     uint32_t a0, uint32_t a1, uint32_t a2, uint32_t a3,
                                     uint32_t b0, uint32_t b1) {
    asm volatile(
        "mma.sync.aligned.m16n8k8.row.col.f32.tf32.tf32.f32 "
        "{%0,%1,%2,%3}, {%4,%5,%6,%7}, {%8,%9}, {%0,%1,%2,%3};\n"
        : "+f"(c[0]), "+f"(c[1]), "+f"(c[2]), "+f"(c[3])
        : "r"(a0), "r"(a1), "r"(a2), "r"(a3), "r"(b0), "r"(b1));
}
// m16n8k16 bf16 mma
__device__ __forceinline__ void mma16(float* c,
                                      uint32_t a0, uint32_t a1, uint32_t a2, uint32_t a3,
                                      uint32_t b0, uint32_t b1) {
    asm volatile(
        "mma.sync.aligned.m16n8k16.row.col.f32.bf16.bf16.f32 "
        "{%0,%1,%2,%3}, {%4,%5,%6,%7}, {%8,%9}, {%0,%1,%2,%3};\n"
        : "+f"(c[0]), "+f"(c[1]), "+f"(c[2]), "+f"(c[3])
        : "r"(a0), "r"(a1), "r"(a2), "r"(a3), "r"(b0), "r"(b1));
}

__device__ __forceinline__ void cp16(uint32_t smem_addr, const void* gptr) {
    asm volatile("cp.async.cg.shared.global [%0], [%1], 16;\n"
                 :: "r"(smem_addr), "l"(gptr));
}
__device__ __forceinline__ void cp_commit() {
    asm volatile("cp.async.commit_group;\n");
}

// ---------------------------------------------------------------------------
// Fused projection GEMM: z in {0,1,2} selects (Q,K,V). (unchanged from R14)
// ---------------------------------------------------------------------------
__global__ __launch_bounds__(256) void proj_fused_kernel(
    const float* __restrict__ Xq, const float* __restrict__ Xk, const float* __restrict__ Xv,
    const float* __restrict__ Wq, const float* __restrict__ bq,
    const float* __restrict__ Wk, const float* __restrict__ bk,
    const float* __restrict__ Wv, const float* __restrict__ bv,
    float* __restrict__ Oq, uint4* __restrict__ Okq, float4* __restrict__ Ov4)
{
    const int z = blockIdx.z;
    const float* X    = (z == 0) ? Xq : (z == 1) ? Xk : Xv;
    const float* W    = (z == 0) ? Wq : (z == 1) ? Wk : Wv;
    const float* bias = (z == 0) ? bq : (z == 1) ? bk : bv;
    const bool PRECISE = (z != 2);

    __shared__ float Xs[2][128][24];
    __shared__ float Ws[2][64][24];

    const int tid  = threadIdx.x;
    const int lane = tid & 31;
    const int warp = tid >> 5;
    const int wm   = warp & 3;
    const int wn   = warp >> 2;
    const int bm   = blockIdx.y * 128;
    const int bn   = blockIdx.x * 64;

    const int g  = lane >> 2;
    const int tg = lane & 3;

    float acc[2][4][4];
#pragma unroll
    for (int i = 0; i < 2; i++)
#pragma unroll
        for (int j = 0; j < 4; j++)
#pragma unroll
            for (int r = 0; r < 4; r++) acc[i][j][r] = 0.f;

    const uint32_t xs_base = (uint32_t)__cvta_generic_to_shared(&Xs[0][0][0]);
    const uint32_t ws_base = (uint32_t)__cvta_generic_to_shared(&Ws[0][0][0]);
    const int xrow0 = tid >> 2,  xc0 = (tid & 3) * 4;
    const int wrow  = tid >> 2,  wc  = (tid & 3) * 4;

    const int NT = DM / 16;   // 48

    auto issue = [&](int kt) {
        const int k0 = kt * 16;
        const uint32_t xb = xs_base + (uint32_t)((kt & 1) * 128 * 24 * 4);
        const uint32_t wb = ws_base + (uint32_t)((kt & 1) * 64 * 24 * 4);
        cp16(xb + (uint32_t)((xrow0      ) * 24 + xc0) * 4,
             X + (size_t)(bm + xrow0) * DM + k0 + xc0);
        cp16(xb + (uint32_t)((xrow0 + 64 ) * 24 + xc0) * 4,
             X + (size_t)(bm + xrow0 + 64) * DM + k0 + xc0);
        cp16(wb + (uint32_t)(wrow * 24 + wc) * 4,
             W + (size_t)(bn + wrow) * DM + k0 + wc);
        cp_commit();
    };

    issue(0);
    issue(1);

    for (int kt = 0; kt < NT; kt++) {
        if (kt + 1 < NT) asm volatile("cp.async.wait_group 1;\n");
        else             asm volatile("cp.async.wait_group 0;\n");
        __syncthreads();
        const int buf = kt & 1;

        if (PRECISE) {
            uint32_t ah[2][4], al[2][4], bh[4][2], bl[4][2];
#pragma unroll
            for (int mt = 0; mt < 2; mt++) {
                const int rb = wm * 32 + mt * 16;
                float2 A0 = *reinterpret_cast<const float2*>(&Xs[buf][rb + g    ][2 * tg]);
                float2 A1 = *reinterpret_cast<const float2*>(&Xs[buf][rb + g + 8][2 * tg]);
                float2 A2 = *reinterpret_cast<const float2*>(&Xs[buf][rb + g    ][2 * tg + 8]);
                float2 A3 = *reinterpret_cast<const float2*>(&Xs[buf][rb + g + 8][2 * tg + 8]);
                bf_split(A0.x, A0.y, ah[mt][0], al[mt][0]);
                bf_split(A1.x, A1.y, ah[mt][1], al[mt][1]);
                bf_split(A2.x, A2.y, ah[mt][2], al[mt][2]);
                bf_split(A3.x, A3.y, ah[mt][3], al[mt][3]);
            }
#pragma unroll
            for (int nt = 0; nt < 4; nt++) {
                const int nb = wn * 32 + nt * 8;
                float2 B0 = *reinterpret_cast<const float2*>(&Ws[buf][nb + g][2 * tg]);
                float2 B1 = *reinterpret_cast<const float2*>(&Ws[buf][nb + g][2 * tg + 8]);
                bf_split(B0.x, B0.y, bh[nt][0], bl[nt][0]);
                bf_split(B1.x, B1.y, bh[nt][1], bl[nt][1]);
            }
#pragma unroll
            for (int mt = 0; mt < 2; mt++)
#pragma unroll
                for (int nt = 0; nt < 4; nt++) {
                    mma16(acc[mt][nt], ah[mt][0], ah[mt][1], ah[mt][2], ah[mt][3],
                          bh[nt][0], bh[nt][1]);
                    mma16(acc[mt][nt], ah[mt][0], ah[mt][1], ah[mt][2], ah[mt][3],
                          bl[nt][0], bl[nt][1]);
                    mma16(acc[mt][nt], al[mt][0], al[mt][1], al[mt][2], al[mt][3],
                          bh[nt][0], bh[nt][1]);
                }
        } else {
#pragma unroll
            for (int ks = 0; ks < 2; ks++) {
                const int kk = ks * 8;
                uint32_t ah[2][4], bh[4][2];
#pragma unroll
                for (int mt = 0; mt < 2; mt++) {
                    const int rb = wm * 32 + mt * 16;
                    ah[mt][0] = rn_bits(Xs[buf][rb + g    ][kk + tg]);
                    ah[mt][1] = rn_bits(Xs[buf][rb + g + 8][kk + tg]);
                    ah[mt][2] = rn_bits(Xs[buf][rb + g    ][kk + tg + 4]);
                    ah[mt][3] = rn_bits(Xs[buf][rb + g + 8][kk + tg + 4]);
                }
#pragma unroll
                for (int nt = 0; nt < 4; nt++) {
                    const int nb = wn * 32 + nt * 8;
                    bh[nt][0] = rn_bits(Ws[buf][nb + g][kk + tg]);
                    bh[nt][1] = rn_bits(Ws[buf][nb + g][kk + tg + 4]);
                }
#pragma unroll
                for (int mt = 0; mt < 2; mt++)
#pragma unroll
                    for (int nt = 0; nt < 4; nt++)
                        mma8(acc[mt][nt], ah[mt][0], ah[mt][1], ah[mt][2], ah[mt][3],
                             bh[nt][0], bh[nt][1]);
            }
        }
        __syncthreads();
        if (kt + 2 < NT) issue(kt + 2);
    }

    // ------------------------- Epilogues -------------------------
    const int hh = bn >> 6;   // head index

    if (z == 1) {
#pragma unroll
        for (int mt = 0; mt < 2; mt++) {
#pragma unroll
            for (int p = 0; p < 2; p++) {
                const int nt0 = 2 * p, nt1 = nt0 + 1;
                const int n0 = bn + wn * 32 + nt0 * 8 + 2 * tg;
                const int n1 = n0 + 8;
                const float b00 = bias[n0], b01 = bias[n0 + 1];
                const float b10 = bias[n1], b11 = bias[n1 + 1];
                const int jj = 8 * wn + 4 * p + tg;     // 0..15
#pragma unroll
                for (int rr = 0; rr < 2; rr++) {
                    const int m  = bm + wm * 32 + mt * 16 + g + rr * 8;
                    const int bb = m / SEQ;
                    const int s  = m % SEQ;
                    uint32_t h0, l0, h1, l1;
                    bf_split(acc[mt][nt0][rr * 2] + b00,
                             acc[mt][nt0][rr * 2 + 1] + b01, h0, l0);
                    bf_split(acc[mt][nt1][rr * 2] + b10,
                             acc[mt][nt1][rr * 2 + 1] + b11, h1, l1);
                    const size_t off =
                        ((size_t)(bb * NH + hh) * SEQ + s) * 16 + jj;
                    Okq[off] = make_uint4(h0, h1, l0, l1);
                }
            }
        }
    } else if (z == 2) {
#pragma unroll
        for (int mt = 0; mt < 2; mt++) {
#pragma unroll
            for (int nt = 0; nt < 4; nt++) {
                const int n = bn + wn * 32 + nt * 8 + 2 * tg;
                const int d = n - hh * 64;
                const float b0 = bias[n];
                const float b1 = bias[n + 1];
                const float fx0 = rn_f(acc[mt][nt][0] + b0);
                const float fy0 = rn_f(acc[mt][nt][1] + b1);
                const float fx1 = rn_f(acc[mt][nt][2] + b0);
                const float fy1 = rn_f(acc[mt][nt][3] + b1);
                const float px0 = __shfl_xor_sync(0xffffffff, fx0, 16);
                const float py0 = __shfl_xor_sync(0xffffffff, fy0, 16);
                const float px1 = __shfl_xor_sync(0xffffffff, fx1, 16);
                const float py1 = __shfl_xor_sync(0xffffffff, fy1, 16);
                if (g < 4) {
                    const int m0 = bm + wm * 32 + mt * 16 + g;
                    const int bb = m0 / SEQ;
                    const int s0 = m0 % SEQ;
                    const size_t R = (size_t)(bb * NH + hh) * (SEQ / 4)
                                   + (s0 >> 4) * 4 + g;
                    Ov4[R * DH + d]     = make_float4(fx0, px0, fx1, px1);
                    Ov4[R * DH + d + 1] = make_float4(fy0, py0, fy1, py1);
                }
            }
        }
    } else {
#pragma unroll
        for (int mt = 0; mt < 2; mt++) {
#pragma unroll
            for (int nt = 0; nt < 4; nt++) {
                const int n = bn + wn * 32 + nt * 8 + 2 * tg;
                const int d = n - hh * 64;
                const float b0 = bias[n];
                const float b1 = bias[n + 1];
#pragma unroll
                for (int rr = 0; rr < 2; rr++) {
                    const int m  = bm + wm * 32 + mt * 16 + g + rr * 8;
                    const int bb = m / SEQ;
                    const int s  = m % SEQ;
                    float2 v = make_float2(acc[mt][nt][rr * 2] + b0,
                                           acc[mt][nt][rr * 2 + 1] + b1);
                    *reinterpret_cast<float2*>(
                        Oq + (((size_t)(bb * NH + hh)) * SEQ + s) * DH + d) = v;
                }
            }
        }
    }
}

// ---------------------------------------------------------------------------
// Flash attention, UNNORMALIZED-EXP variant. No scaling + bounded inputs =>
// scores |s| < ~60 and exp(s) < e^60 << fp32 max, so the online max is
// unnecessary: P = exp(s) directly, normalize by the accumulated row sum once
// at the end. Removes per tile: max tree (8 FMAX + 4 SHFL), corr (2 MUFU),
// oacc rescale (32 FMUL, a serial gate before PV), sum shuffles (deferred to
// epilogue). Inter-mma phase: 16 MUFU + 16 FADD + 8 IADD + 4 STS.64.
// ---------------------------------------------------------------------------
__global__ __launch_bounds__(128, 4) void flash_mma_kernel(
    const float* __restrict__ Qh,
    const uint4* __restrict__ KqG,
    const float4* __restrict__ VqG,
    float* __restrict__ out)
{
    __shared__ uint4  KqS[2][32][20];     // 20480 B
    __shared__ float4 VqS[2][8][66];      // 16896 B
    __shared__ float  Ps[4][16][36];      //  9216 B

    const int tid  = threadIdx.x;
    const int lane = tid & 31;
    const int warp = tid >> 5;
    const int g    = lane >> 2;
    const int tg   = lane & 3;

    const int b  = blockIdx.z;
    const int h  = blockIdx.y;
    const int q0 = blockIdx.x * 64;
    const size_t baseq = ((size_t)(b * NH + h)) * SEQ * DH;
    const size_t basek = ((size_t)(b * NH + h)) * SEQ * 16;
    const size_t basev = ((size_t)(b * NH + h)) * (SEQ / 4) * DH;

    const uint32_t kq_base = (uint32_t)__cvta_generic_to_shared(&KqS[0][0][0]);
    const uint32_t vq_base = (uint32_t)__cvta_generic_to_shared(&VqS[0][0][0]);

    auto issue = [&](int kt) {
        const uint32_t kb = kq_base + (uint32_t)((kt & 1) * 32 * 20 * 16);
        const uint32_t vb = vq_base + (uint32_t)((kt & 1) * 8 * 66 * 16);
        const uint4*  kp = KqG + basek + (size_t)kt * 32 * 16;
        const float4* vp = VqG + basev + (size_t)kt * 8 * DH;
#pragma unroll
        for (int i = 0; i < 4; i++) {
            const int idx = i * 128 + tid;
            const int row = idx >> 4;
            const int c   = idx & 15;
            cp16(kb + (uint32_t)(row * 20 + c) * 16, kp + row * 16 + c);
        }
#pragma unroll
        for (int i = 0; i < 4; i++) {
            const int idx = i * 128 + tid;
            const int row = idx >> 6;
            const int c   = idx & 63;
            cp16(vb + (uint32_t)(row * 66 + c) * 16, vp + row * DH + c);
        }
        cp_commit();
    };

    // Hoisted Q fragments (bf16 hi/lo)
    uint32_t qh[4][4], ql[4][4];
    {
        const float* q0p = Qh + baseq + (size_t)(q0 + warp * 16 + g) * DH;
        const float* q1p = q0p + 8 * DH;
#pragma unroll
        for (int s = 0; s < 4; s++) {
            const int c0 = s * 16 + 2 * tg;
            float2 A0 = *reinterpret_cast<const float2*>(q0p + c0);
            float2 A1 = *reinterpret_cast<const float2*>(q1p + c0);
            float2 A2 = *reinterpret_cast<const float2*>(q0p + c0 + 8);
            float2 A3 = *reinterpret_cast<const float2*>(q1p + c0 + 8);
            bf_split(A0.x, A0.y, qh[s][0], ql[s][0]);
            bf_split(A1.x, A1.y, qh[s][1], ql[s][1]);
            bf_split(A2.x, A2.y, qh[s][2], ql[s][2]);
            bf_split(A3.x, A3.y, qh[s][3], ql[s][3]);
        }
    }

    issue(0);
    issue(1);

    float oacc[8][4];
#pragma unroll
    for (int dt = 0; dt < 8; dt++)
#pragma unroll
        for (int r = 0; r < 4; r++) oacc[dt][r] = 0.f;
    float lrow0 = 0.f, lrow1 = 0.f;   // per-lane PARTIAL row sums

    const int NT = SEQ / 32;   // 64

    for (int kt = 0; kt < NT; kt++) {
        if (kt + 1 < NT) asm volatile("cp.async.wait_group 1;\n");
        else             asm volatile("cp.async.wait_group 0;\n");
        __syncthreads();
        const int buf = kt & 1;

        // ---- Scores ----
        float sacc[4][4];
#pragma unroll
        for (int nt = 0; nt < 4; nt++)
#pragma unroll
            for (int r = 0; r < 4; r++) sacc[nt][r] = 0.f;

#pragma unroll
        for (int s = 0; s < 4; s++) {
#pragma unroll
            for (int nt = 0; nt < 4; nt++) {
                uint4 w = KqS[buf][nt * 8 + g][s * 4 + tg];
                mma16(sacc[nt], qh[s][0], qh[s][1], qh[s][2], qh[s][3], w.x, w.y);
                mma16(sacc[nt], qh[s][0], qh[s][1], qh[s][2], qh[s][3], w.z, w.w);
                mma16(sacc[nt], ql[s][0], ql[s][1], ql[s][2], ql[s][3], w.x, w.y);
            }
        }

        // ---- Unnormalized exp + partial row sums + P store ----
#pragma unroll
        for (int nt = 0; nt < 4; nt++) {
            float p0 = __expf(sacc[nt][0]);
            float p1 = __expf(sacc[nt][1]);
            float p2 = __expf(sacc[nt][2]);
            float p3 = __expf(sacc[nt][3]);
            lrow0 += p0 + p1;
            lrow1 += p2 + p3;
            const int col = nt * 8 + 2 * tg;
            *reinterpret_cast<uint2*>(&Ps[warp][g][col]) =
                make_uint2(rn_bits(p0), rn_bits(p1));
            *reinterpret_cast<uint2*>(&Ps[warp][g + 8][col]) =
                make_uint2(rn_bits(p2), rn_bits(p3));
        }
        __syncwarp();

        // ---- PV: 1 LDS.128 feeds 2 mma8 per (half,dt) ----
#pragma unroll
        for (int half = 0; half < 2; half++) {
            const int kc0 = half * 16;
            const int kc1 = half * 16 + 8;
            uint32_t a00 = __float_as_uint(Ps[warp][g][kc0 + tg]);
            uint32_t a01 = __float_as_uint(Ps[warp][g + 8][kc0 + tg]);
            uint32_t a02 = __float_as_uint(Ps[warp][g][kc0 + tg + 4]);
            uint32_t a03 = __float_as_uint(Ps[warp][g + 8][kc0 + tg + 4]);
            uint32_t a10 = __float_as_uint(Ps[warp][g][kc1 + tg]);
            uint32_t a11 = __float_as_uint(Ps[warp][g + 8][kc1 + tg]);
            uint32_t a12 = __float_as_uint(Ps[warp][g][kc1 + tg + 4]);
            uint32_t a13 = __float_as_uint(Ps[warp][g + 8][kc1 + tg + 4]);
#pragma unroll
            for (int dt = 0; dt < 8; dt++) {
                float4 v4 = VqS[buf][half * 4 + tg][dt * 8 + g];
                mma8(oacc[dt], a00, a01, a02, a03,
                     __float_as_uint(v4.x), __float_as_uint(v4.y));
                mma8(oacc[dt], a10, a11, a12, a13,
                     __float_as_uint(v4.z), __float_as_uint(v4.w));
            }
        }

        __syncthreads();
        if (kt + 2 < NT) issue(kt + 2);
    }

    // Epilogue: one cross-lane reduction of the row sums, then normalize.
    lrow0 += __shfl_xor_sync(0xffffffff, lrow0, 1);
    lrow0 += __shfl_xor_sync(0xffffffff, lrow0, 2);
    lrow1 += __shfl_xor_sync(0xffffffff, lrow1, 1);
    lrow1 += __shfl_xor_sync(0xffffffff, lrow1, 2);
    const float inv0 = 1.f / lrow0;
    const float inv1 = 1.f / lrow1;
    const int row0 = q0 + warp * 16 + g;
    const int row1 = row0 + 8;
    float* o0 = out + ((size_t)(b * SEQ + row0)) * DM + h * DH;
    float* o1 = out + ((size_t)(b * SEQ + row1)) * DM + h * DH;
#pragma unroll
    for (int dt = 0; dt < 8; dt++) {
        const int col = dt * 8 + 2 * tg;
        float2 v0, v1;
        v0.x = oacc[dt][0] * inv0; v0.y = oacc[dt][1] * inv0;
        v1.x = oacc[dt][2] * inv1; v1.y = oacc[dt][3] * inv1;
        *reinterpret_cast<float2*>(o0 + col) = v0;
        *reinterpret_cast<float2*>(o1 + col) = v1;
    }
}

// ---------------------------------------------------------------------------
// Launch
// ---------------------------------------------------------------------------
extern "C" void kernel_launch(void* const* d_in, const int* in_sizes, int n_in,
                              void* d_out, int out_size)
{
    const float* q  = (const float*)d_in[0];
    const float* k  = (const float*)d_in[1];
    const float* v  = (const float*)d_in[2];
    const float* Wq = (const float*)d_in[3];
    const float* bq = (const float*)d_in[4];
    const float* Wk = (const float*)d_in[5];
    const float* bk = (const float*)d_in[6];
    const float* Wv = (const float*)d_in[7];
    const float* bv = (const float*)d_in[8];
    float* out = (float*)d_out;

    float  *dq;
    uint4  *dkq;
    float4 *dv4;
    cudaGetSymbolAddress((void**)&dq,  g_wq);
    cudaGetSymbolAddress((void**)&dkq, g_wk_q);
    cudaGetSymbolAddress((void**)&dv4, g_wv4);

    dim3 pgrid(DM / 64, M_TOTAL / 128, 3);     // (12, 64, 3)
    proj_fused_kernel<<<pgrid, 256>>>(q, k, v, Wq, bq, Wk, bk, Wv, bv,
                                      dq, dkq, dv4);

    dim3 agrid(SEQ / 64, NH, BATCH);           // (32, 12, 4)
    flash_mma_kernel<<<agrid, 128>>>(dq, dkq, dv4, out);
}